// round 7
// baseline (speedup 1.0000x reference)
#include <cuda_runtime.h>
#include <cuda_bf16.h>
#include <math.h>

// Problem constants
#define BB   32      // batch
#define SS   64      // src len
#define TT   64      // tgt len (63 decode steps)
#define EE   512     // embed dim
#define HH   512     // encoder hidden per dir
#define DDm  1024    // 2*H
#define VV   32000   // vocab

typedef unsigned long long ull;

// packed fp32x2 helpers (sm_103a FFMA2; numerically identical to scalar FMA)
__device__ __forceinline__ ull pk2(float x, float y) {
    ull r; asm("mov.b64 %0, {%1, %2};" : "=l"(r) : "f"(x), "f"(y)); return r;
}
__device__ __forceinline__ void fma2(ull& d, ull a, ull b) {
    asm("fma.rn.f32x2 %0, %1, %2, %0;" : "+l"(d) : "l"(a), "l"(b));
}
__device__ __forceinline__ float2 upk2(ull v) {
    float x, y; asm("mov.b64 {%0, %1}, %2;" : "=f"(x), "=f"(y) : "l"(v));
    return make_float2(x, y);
}

// ---------------------------------------------------------------------------
// Static device scratch
// ---------------------------------------------------------------------------
__device__ __align__(16) float g_embx [BB*SS*EE];
__device__ __align__(16) float g_xgF  [BB*SS*4*HH];
__device__ __align__(16) float g_xgB  [BB*SS*4*HH];
__device__ __align__(16) float g_in1  [BB*SS*DDm];
__device__ __align__(16) float g_enc  [BB*SS*DDm];
__device__ __align__(16) float g_Uenc [BB*SS*DDm];
__device__ __align__(16) float g_hbuf [2*2*2*BB*HH];   // [layer][dir][pp][b*512+j]
__device__ __align__(16) float g_c    [2*2*BB*HH];     // final enc cell states
__device__ __align__(16) float g_dh0  [2*BB*DDm];      // ping-pong
__device__ __align__(16) float g_dc0  [BB*DDm];
__device__ __align__(16) float g_dh1  [2*BB*DDm];      // ping-pong
__device__ __align__(16) float g_dc1  [BB*DDm];
__device__ __align__(16) float g_q    [BB*DDm];
__device__ __align__(16) float g_sc   [BB*SS];
__device__ __align__(16) float g_xcat [BB*(EE+DDm)];   // [32][1536]
__device__ __align__(16) float g_H1   [63*BB*DDm];
__device__ unsigned g_bar;

__device__ __forceinline__ float sigf(float v) { return 1.0f/(1.0f + expf(-v)); }

// ---------------------------------------------------------------------------
// grid-wide software barrier (cooperative-groups grid.sync pattern)
// ---------------------------------------------------------------------------
__device__ __forceinline__ void gbar(unsigned tgt) {
    __syncthreads();
    if (threadIdx.x == 0) {
        asm volatile("red.release.gpu.add.u32 [%0], %1;" :: "l"(&g_bar), "r"(1u) : "memory");
        unsigned v;
        do {
            asm volatile("ld.acquire.gpu.u32 %0, [%1];" : "=r"(v) : "l"(&g_bar) : "memory");
        } while (v < tgt);
    }
    __syncthreads();
}

// ---------------------------------------------------------------------------
// 4-gate dot accumulate over one 256-k chunk.
// W rows: g*NH + j, row stride rstride. sh = [k][b] transposed chunk.
// ---------------------------------------------------------------------------
__device__ __forceinline__ void accum4(
    const float* __restrict__ W, size_t rstride, int NH, int j, int koff,
    const float* __restrict__ sh, int b,
    float& a0, float& a1, float& a2, float& a3)
{
    const float4* w0 = (const float4*)(W + (size_t)(0*NH + j)*rstride + koff);
    const float4* w1 = (const float4*)(W + (size_t)(1*NH + j)*rstride + koff);
    const float4* w2 = (const float4*)(W + (size_t)(2*NH + j)*rstride + koff);
    const float4* w3 = (const float4*)(W + (size_t)(3*NH + j)*rstride + koff);
    #pragma unroll 4
    for (int k4 = 0; k4 < 64; k4++) {
        float4 v0 = w0[k4], v1 = w1[k4], v2 = w2[k4], v3 = w3[k4];
        float h0 = sh[(k4*4+0)*33 + b];
        float h1 = sh[(k4*4+1)*33 + b];
        float h2 = sh[(k4*4+2)*33 + b];
        float h3 = sh[(k4*4+3)*33 + b];
        a0 += v0.x*h0 + v0.y*h1 + v0.z*h2 + v0.w*h3;
        a1 += v1.x*h0 + v1.y*h1 + v1.z*h2 + v1.w*h3;
        a2 += v2.x*h0 + v2.y*h1 + v2.z*h2 + v2.w*h3;
        a3 += v3.x*h0 + v3.y*h1 + v3.z*h2 + v3.w*h3;
    }
}

// ---------------------------------------------------------------------------
// 1) embedding gather with source reversal
// ---------------------------------------------------------------------------
__global__ void embed_rev_kernel(const int* __restrict__ x,
                                 const float* __restrict__ emb_src) {
    int bs = blockIdx.x;
    int b = bs >> 6, s = bs & 63;
    int tok = x[b*SS + (SS-1 - s)];
    const float4* src = (const float4*)(emb_src + (size_t)tok*EE);
    float4* dst = (float4*)(g_embx + (size_t)bs*EE);
    for (int i = threadIdx.x; i < EE/4; i += blockDim.x) dst[i] = src[i];
}

// ---------------------------------------------------------------------------
// 2) SGEMM (TN) with packed f32x2 FMA (unchanged, proven)
// ---------------------------------------------------------------------------
__global__ __launch_bounds__(256) void sgemm128(
    const float* __restrict__ A, const float* __restrict__ W,
    const float* __restrict__ bias, float* __restrict__ C,
    int M, int N, int K, int remap)
{
    __shared__ float As[8][132];
    __shared__ float Ws[8][132];
    int tid = threadIdx.x;
    int tx = tid & 15;
    int ty = tid >> 4;
    int m0 = blockIdx.x * 128;
    int n0 = blockIdx.y * 128;

    ull acc2[8][4];
    #pragma unroll
    for (int i = 0; i < 8; i++)
        #pragma unroll
        for (int j = 0; j < 4; j++) acc2[i][j] = 0ULL;

    int lr  = tid >> 1;
    int lk  = (tid & 1) * 4;

    for (int k0 = 0; k0 < K; k0 += 8) {
        float4 va;
        int gm = m0 + lr;
        if (gm < M) va = *(const float4*)(A + (size_t)gm*K + k0 + lk);
        else        va = make_float4(0.f,0.f,0.f,0.f);
        As[lk+0][lr]=va.x; As[lk+1][lr]=va.y; As[lk+2][lr]=va.z; As[lk+3][lr]=va.w;
        float4 vw = *(const float4*)(W + (size_t)(n0+lr)*K + k0 + lk);
        Ws[lk+0][lr]=vw.x; Ws[lk+1][lr]=vw.y; Ws[lk+2][lr]=vw.z; Ws[lk+3][lr]=vw.w;
        __syncthreads();

        #pragma unroll
        for (int kk = 0; kk < 8; kk++) {
            float4 a03 = *(const float4*)&As[kk][ty*8];
            float4 a47 = *(const float4*)&As[kk][ty*8+4];
            float4 w03 = *(const float4*)&Ws[kk][tx*8];
            float4 w47 = *(const float4*)&Ws[kk][tx*8+4];
            ull w01 = pk2(w03.x, w03.y);
            ull w23 = pk2(w03.z, w03.w);
            ull w45 = pk2(w47.x, w47.y);
            ull w67 = pk2(w47.z, w47.w);
            float av[8] = {a03.x,a03.y,a03.z,a03.w,a47.x,a47.y,a47.z,a47.w};
            #pragma unroll
            for (int i = 0; i < 8; i++) {
                ull aa = pk2(av[i], av[i]);
                fma2(acc2[i][0], aa, w01);
                fma2(acc2[i][1], aa, w23);
                fma2(acc2[i][2], aa, w45);
                fma2(acc2[i][3], aa, w67);
            }
        }
        __syncthreads();
    }

    #pragma unroll
    for (int i = 0; i < 8; i++) {
        int gm = m0 + ty*8 + i;
        if (gm >= M) continue;
        int orow = gm;
        if (remap) orow = (gm & 31)*63 + (gm >> 5);
        float* cr = C + (size_t)orow*N + n0 + tx*8;
        #pragma unroll
        for (int jp = 0; jp < 4; jp++) {
            float2 v = upk2(acc2[i][jp]);
            cr[2*jp+0] = v.x + bias[n0 + tx*8 + 2*jp+0];
            cr[2*jp+1] = v.y + bias[n0 + tx*8 + 2*jp+1];
        }
    }
}

// ---------------------------------------------------------------------------
// 3) Persistent encoder layer: grid (64, 2) = 128 blocks, loops all 64 steps.
//    c stays in registers; whh slice (64KB/block) stays L1-resident.
// ---------------------------------------------------------------------------
#define NBE 128u
__global__ __launch_bounds__(256) void enc_persist(
    const float* __restrict__ whhF, const float* __restrict__ whhB, int layer)
{
    __shared__ float sh[256*33];
    int tid = threadIdx.x;
    int dir = blockIdx.y;
    const float* whh = dir ? whhB : whhF;
    const float* xg  = dir ? g_xgB : g_xgF;
    float* cfin = g_c + (size_t)(layer*2+dir) * (BB*HH);
    float* outb = layer ? g_enc : g_in1;

    int b = tid & 31;
    int j = blockIdx.x*8 + (tid >> 5);
    float creg = 0.f;
    unsigned tgt = 0;

    for (int step = 0; step < SS; step++) {
        int pp = step & 1;
        const float* hin  = g_hbuf + (size_t)(((layer*2+dir)*2) + pp)    * (BB*HH);
        float*       hout = g_hbuf + (size_t)(((layer*2+dir)*2) + (pp^1))* (BB*HH);
        int s = dir ? (63 - step) : step;

        float a0=0.f, a1=0.f, a2=0.f, a3=0.f;
        for (int ch = 0; ch < 2; ch++) {
            for (int i = tid; i < 256*32; i += 256) {
                int bb = i >> 8, kk = i & 255;
                sh[kk*33 + bb] = __ldcg(&hin[bb*HH + ch*256 + kk]);
            }
            __syncthreads();
            accum4(whh, HH, HH, j, ch*256, sh, b, a0, a1, a2, a3);
            __syncthreads();
        }

        size_t row = (size_t)(b*SS + s) * (4*HH);
        float gi = xg[row + 0*HH + j] + a0;
        float gf = xg[row + 1*HH + j] + a1;
        float gg = xg[row + 2*HH + j] + a2;
        float go = xg[row + 3*HH + j] + a3;
        creg = sigf(gf)*creg + sigf(gi)*tanhf(gg);
        float hh = sigf(go)*tanhf(creg);
        hout[b*HH + j] = hh;
        outb[(size_t)(b*SS + s)*DDm + dir*HH + j] = hh;

        tgt += NBE;
        gbar(tgt);
    }
    cfin[b*HH + j] = creg;
}

// ---------------------------------------------------------------------------
// 4) Decoder initial state (reads pp=0 slot written after 64 enc steps)
// ---------------------------------------------------------------------------
__global__ void dec_init() {
    int idx = blockIdx.x*256 + threadIdx.x;
    if (idx >= BB*HH) return;
    int b = idx >> 9, j = idx & 511;
    const int NP = BB*HH;
    float h0f = g_hbuf[(size_t)((0*2+0)*2+0)*NP + idx];
    float h0b = g_hbuf[(size_t)((0*2+1)*2+0)*NP + idx];
    float h1f = g_hbuf[(size_t)((1*2+0)*2+0)*NP + idx];
    float h1b = g_hbuf[(size_t)((1*2+1)*2+0)*NP + idx];
    float c0f = g_c[(size_t)(0*2+0)*NP + idx];
    float c0b = g_c[(size_t)(0*2+1)*NP + idx];
    float c1f = g_c[(size_t)(1*2+0)*NP + idx];
    float c1b = g_c[(size_t)(1*2+1)*NP + idx];
    g_dh0[b*DDm + j]      = h0f;  g_dh0[b*DDm + HH + j] = h0b;
    g_dc0[b*DDm + j]      = c0f;  g_dc0[b*DDm + HH + j] = c0b;
    g_dh1[b*DDm + j]      = h1f;  g_dh1[b*DDm + HH + j] = h1b;
    g_dc1[b*DDm + j]      = c1f;  g_dc1[b*DDm + HH + j] = c1b;
}

// ---------------------------------------------------------------------------
// 5) Persistent decoder: grid 128 blocks, 63 steps x 5 phases internally.
//    c0/c1 live in registers. h0/h1 ping-pong in global (__ldcg reads).
// ---------------------------------------------------------------------------
#define NBD 128u
__global__ __launch_bounds__(256) void dec_persist(
    const int*   __restrict__ y,      const float* __restrict__ emb_tgt,
    const float* __restrict__ Wa_w,   const float* __restrict__ Wa_b,
    const float* __restrict__ va,
    const float* __restrict__ d0_wih, const float* __restrict__ d0_whh,
    const float* __restrict__ d0_b,
    const float* __restrict__ d1_wih, const float* __restrict__ d1_whh,
    const float* __restrict__ d1_b)
{
    __shared__ float sh[256*33];
    __shared__ float wsm[SS];
    int tid = threadIdx.x;
    int bid = blockIdx.x;
    int b31 = tid & 31;
    int jj  = tid >> 5;
    int j8  = bid*8 + jj;            // 0..1023
    unsigned tgt = 0;

    float c0 = __ldcg(&g_dc0[b31*DDm + j8]);
    float c1 = __ldcg(&g_dc1[b31*DDm + j8]);

    for (int t = 0; t < TT-1; t++) {
        int pp = t & 1;
        const float* h1r = g_dh1 + (size_t)pp*(BB*DDm);
        const float* h0r = g_dh0 + (size_t)pp*(BB*DDm);
        float*       h0w = g_dh0 + (size_t)(pp^1)*(BB*DDm);
        float*       h1w = g_dh1 + (size_t)(pp^1)*(BB*DDm);

        // ---- Phase A: q[b][j8] = h1r[b] . Wa_w[j8] + Wa_b[j8]
        {
            float acc = 0.f;
            const float* w = Wa_w + (size_t)j8*DDm;
            for (int ch = 0; ch < 4; ch++) {
                for (int i = tid; i < 256*32; i += 256) {
                    int bb = i >> 8, kk = i & 255;
                    sh[kk*33 + bb] = __ldcg(&h1r[bb*DDm + ch*256 + kk]);
                }
                __syncthreads();
                const float4* w4 = (const float4*)(w + ch*256);
                #pragma unroll 8
                for (int k4 = 0; k4 < 64; k4++) {
                    float4 v = w4[k4];
                    acc += v.x*sh[(k4*4+0)*33+b31] + v.y*sh[(k4*4+1)*33+b31]
                         + v.z*sh[(k4*4+2)*33+b31] + v.w*sh[(k4*4+3)*33+b31];
                }
                __syncthreads();
            }
            g_q[b31*DDm + j8] = acc + Wa_b[j8];
        }
        tgt += NBD; gbar(tgt);

        // ---- Phase B: scores (warp per (b,s), 16 tasks/block)
        {
            int lane = tid & 31, w = tid >> 5;
            #pragma unroll
            for (int r = 0; r < 2; r++) {
                int task = bid*16 + w*2 + r;         // 0..2047 = b*64+s
                int b = task >> 6;
                const float* u  = g_Uenc + (size_t)task*DDm;
                const float* qq = g_q + (size_t)b*DDm;
                float p = 0.f;
                for (int e = lane; e < DDm; e += 32)
                    p += va[e]*tanhf(__ldcg(&qq[e]) + u[e]);
                #pragma unroll
                for (int off = 16; off; off >>= 1)
                    p += __shfl_xor_sync(0xffffffffu, p, off);
                if (lane == 0) g_sc[task] = p;
            }
        }
        tgt += NBD; gbar(tgt);

        // ---- Phase C: softmax (in-block) + context + embedding gather
        {
            int b = bid >> 2, quarter = bid & 3;
            if (tid < SS) wsm[tid] = __ldcg(&g_sc[b*SS + tid]);
            __syncthreads();
            if (tid == 0) {
                float mx = wsm[0];
                for (int s = 1; s < SS; s++) mx = fmaxf(mx, wsm[s]);
                float sm = 0.f;
                for (int s = 0; s < SS; s++) { wsm[s] = expf(wsm[s]-mx); sm += wsm[s]; }
                float inv = 1.0f/sm;
                for (int s = 0; s < SS; s++) wsm[s] *= inv;
            }
            __syncthreads();
            int d = quarter*256 + tid;
            float acc = 0.f;
            const float* e = g_enc + (size_t)(b*SS)*DDm + d;
            #pragma unroll 8
            for (int s = 0; s < SS; s++) acc += wsm[s]*e[(size_t)s*DDm];
            g_xcat[(size_t)b*(EE+DDm) + EE + d] = acc;
            if (quarter < 2) {
                int ei = quarter*256 + tid;
                int tok = y[b*TT + t];
                g_xcat[(size_t)b*(EE+DDm) + ei] = emb_tgt[(size_t)tok*EE + ei];
            }
            __syncthreads();
        }
        tgt += NBD; gbar(tgt);

        // ---- Phase D: gates0 (xcat@wih + h0_old@whh + b) + cell0, fused
        {
            float a0=0.f, a1=0.f, a2=0.f, a3=0.f;
            for (int ch = 0; ch < 6; ch++) {          // xcat, K=1536
                for (int i = tid; i < 256*32; i += 256) {
                    int bb = i >> 8, kk = i & 255;
                    sh[kk*33 + bb] = __ldcg(&g_xcat[(size_t)bb*(EE+DDm) + ch*256 + kk]);
                }
                __syncthreads();
                accum4(d0_wih, EE+DDm, DDm, j8, ch*256, sh, b31, a0, a1, a2, a3);
                __syncthreads();
            }
            for (int ch = 0; ch < 4; ch++) {          // h0_old, K=1024
                for (int i = tid; i < 256*32; i += 256) {
                    int bb = i >> 8, kk = i & 255;
                    sh[kk*33 + bb] = __ldcg(&h0r[bb*DDm + ch*256 + kk]);
                }
                __syncthreads();
                accum4(d0_whh, DDm, DDm, j8, ch*256, sh, b31, a0, a1, a2, a3);
                __syncthreads();
            }
            float gi = a0 + d0_b[0*DDm + j8];
            float gf = a1 + d0_b[1*DDm + j8];
            float gg = a2 + d0_b[2*DDm + j8];
            float go = a3 + d0_b[3*DDm + j8];
            c0 = sigf(gf)*c0 + sigf(gi)*tanhf(gg);
            h0w[b31*DDm + j8] = sigf(go)*tanhf(c0);
        }
        tgt += NBD; gbar(tgt);

        // ---- Phase E: gates1 (h0_new@wih + h1_old@whh + b) + cell1 + H1
        {
            float a0=0.f, a1=0.f, a2=0.f, a3=0.f;
            for (int ch = 0; ch < 4; ch++) {          // h0_new, K=1024
                for (int i = tid; i < 256*32; i += 256) {
                    int bb = i >> 8, kk = i & 255;
                    sh[kk*33 + bb] = __ldcg(&h0w[bb*DDm + ch*256 + kk]);
                }
                __syncthreads();
                accum4(d1_wih, DDm, DDm, j8, ch*256, sh, b31, a0, a1, a2, a3);
                __syncthreads();
            }
            for (int ch = 0; ch < 4; ch++) {          // h1_old, K=1024
                for (int i = tid; i < 256*32; i += 256) {
                    int bb = i >> 8, kk = i & 255;
                    sh[kk*33 + bb] = __ldcg(&h1r[bb*DDm + ch*256 + kk]);
                }
                __syncthreads();
                accum4(d1_whh, DDm, DDm, j8, ch*256, sh, b31, a0, a1, a2, a3);
                __syncthreads();
            }
            float gi = a0 + d1_b[0*DDm + j8];
            float gf = a1 + d1_b[1*DDm + j8];
            float gg = a2 + d1_b[2*DDm + j8];
            float go = a3 + d1_b[3*DDm + j8];
            c1 = sigf(gf)*c1 + sigf(gi)*tanhf(gg);
            float hh = sigf(go)*tanhf(c1);
            h1w[b31*DDm + j8] = hh;
            g_H1[((size_t)t*BB + b31)*DDm + j8] = hh;
        }
        tgt += NBD; gbar(tgt);
    }
}

// ---------------------------------------------------------------------------
// host driver
// ---------------------------------------------------------------------------
static float* symf(const void* s) {
    void* p = nullptr;
    cudaGetSymbolAddress(&p, s);
    return (float*)p;
}

extern "C" void kernel_launch(void* const* d_in, const int* in_sizes, int n_in,
                              void* d_out, int out_size) {
    const int*   x        = (const int*)  d_in[0];
    const int*   y        = (const int*)  d_in[1];
    const float* emb_src  = (const float*)d_in[2];
    const float* emb_tgt  = (const float*)d_in[3];
    const float* e0f_wih  = (const float*)d_in[4];
    const float* e0f_whh  = (const float*)d_in[5];
    const float* e0f_b    = (const float*)d_in[6];
    const float* e0b_wih  = (const float*)d_in[7];
    const float* e0b_whh  = (const float*)d_in[8];
    const float* e0b_b    = (const float*)d_in[9];
    const float* e1f_wih  = (const float*)d_in[10];
    const float* e1f_whh  = (const float*)d_in[11];
    const float* e1f_b    = (const float*)d_in[12];
    const float* e1b_wih  = (const float*)d_in[13];
    const float* e1b_whh  = (const float*)d_in[14];
    const float* e1b_b    = (const float*)d_in[15];
    const float* Wa_w     = (const float*)d_in[16];
    const float* Wa_b     = (const float*)d_in[17];
    const float* Ua_w     = (const float*)d_in[18];
    const float* Ua_b     = (const float*)d_in[19];
    const float* va_w     = (const float*)d_in[20];
    const float* d0_wih   = (const float*)d_in[21];
    const float* d0_whh   = (const float*)d_in[22];
    const float* d0_b     = (const float*)d_in[23];
    const float* d1_wih   = (const float*)d_in[24];
    const float* d1_whh   = (const float*)d_in[25];
    const float* d1_b     = (const float*)d_in[26];
    const float* fc_w     = (const float*)d_in[27];
    const float* fc_b     = (const float*)d_in[28];
    float* out = (float*)d_out;

    float* p_embx = symf(g_embx);
    float* p_xgF  = symf(g_xgF);
    float* p_xgB  = symf(g_xgB);
    float* p_in1  = symf(g_in1);
    float* p_enc  = symf(g_enc);
    float* p_Uenc = symf(g_Uenc);
    float* p_hbuf = symf(g_hbuf);
    float* p_H1   = symf(g_H1);
    void*  p_bar  = nullptr; cudaGetSymbolAddress(&p_bar, g_bar);

    const int M = BB*SS;     // 2048

    // 1) embedding + reverse
    embed_rev_kernel<<<BB*SS, 128>>>(x, emb_src);

    // 2) layer-0 input GEMMs
    {
        dim3 grid(M/128, (4*HH)/128);
        sgemm128<<<grid, 256>>>(p_embx, e0f_wih, e0f_b, p_xgF, M, 4*HH, EE, 0);
        sgemm128<<<grid, 256>>>(p_embx, e0b_wih, e0b_b, p_xgB, M, 4*HH, EE, 0);
    }

    cudaMemsetAsync(p_hbuf, 0, sizeof(float)*2*2*2*BB*HH);

    // 3) layer-0 recurrence (persistent)
    cudaMemsetAsync(p_bar, 0, sizeof(unsigned));
    enc_persist<<<dim3(64, 2), 256>>>(e0f_whh, e0b_whh, 0);

    // 4) layer-1 input GEMMs
    {
        dim3 grid(M/128, (4*HH)/128);
        sgemm128<<<grid, 256>>>(p_in1, e1f_wih, e1f_b, p_xgF, M, 4*HH, DDm, 0);
        sgemm128<<<grid, 256>>>(p_in1, e1b_wih, e1b_b, p_xgB, M, 4*HH, DDm, 0);
    }

    // 5) layer-1 recurrence (persistent)
    cudaMemsetAsync(p_bar, 0, sizeof(unsigned));
    enc_persist<<<dim3(64, 2), 256>>>(e1f_whh, e1b_whh, 1);

    // 6) Uenc = enc @ Ua^T + Ua_b
    {
        dim3 grid(M/128, DDm/128);
        sgemm128<<<grid, 256>>>(p_enc, Ua_w, Ua_b, p_Uenc, M, DDm, DDm, 0);
    }

    // 7) decoder initial state
    dec_init<<<(BB*HH + 255)/256, 256>>>();

    // 8) decoder (persistent, all 63 steps)
    cudaMemsetAsync(p_bar, 0, sizeof(unsigned));
    dec_persist<<<128, 256>>>(y, emb_tgt, Wa_w, Wa_b, va_w,
                              d0_wih, d0_whh, d0_b, d1_wih, d1_whh, d1_b);

    // 9) deferred logits GEMM
    {
        int Mf = 63*BB;   // 2016
        dim3 grid((Mf + 127)/128, VV/128);
        sgemm128<<<grid, 256>>>(p_H1, fc_w, fc_b, out, Mf, VV, DDm, 1);
    }
}

// round 8
// speedup vs baseline: 2.2029x; 2.2029x over previous
#include <cuda_runtime.h>
#include <cuda_bf16.h>
#include <math.h>

// Problem constants
#define BB   32      // batch
#define SS   64      // src len
#define TT   64      // tgt len (63 decode steps)
#define EE   512     // embed dim
#define HH   512     // encoder hidden per dir
#define DDm  1024    // 2*H
#define VV   32000   // vocab

typedef unsigned long long ull;

// ---------------------------------------------------------------------------
// Static device scratch
// ---------------------------------------------------------------------------
__device__ __align__(16) float g_embx [BB*SS*EE];
__device__ __align__(16) float g_xgF  [BB*SS*4*HH];
__device__ __align__(16) float g_xgB  [BB*SS*4*HH];
__device__ __align__(16) float g_in1  [BB*SS*DDm];
__device__ __align__(16) float g_enc  [BB*SS*DDm];
__device__ __align__(16) float g_Uenc [BB*SS*DDm];
__device__ __align__(16) float g_hbuf [2*2*2*BB*HH];   // [layer][dir][pp][b*512+j]
__device__ __align__(16) float g_c    [2*2*BB*HH];
__device__ __align__(16) float g_dh0  [BB*DDm];
__device__ __align__(16) float g_dc0  [BB*DDm];
__device__ __align__(16) float g_dh1  [BB*DDm];
__device__ __align__(16) float g_dc1  [BB*DDm];
__device__ __align__(16) float g_q    [BB*DDm];
__device__ __align__(16) float g_sc   [BB*SS];
__device__ __align__(16) float g_xcat [BB*(EE+DDm)];
__device__ __align__(16) float g_gA   [BB*4*DDm];
__device__ __align__(16) float g_gB   [BB*4*DDm];
__device__ __align__(16) float g_H1   [63*BB*DDm];

__device__ __forceinline__ float sigf(float v) { return 1.0f/(1.0f + expf(-v)); }

// fp32 -> (bf16 hi, bf16 lo) packed pairs
__device__ __forceinline__ void cvt2(float f0, float f1, unsigned& hi, unsigned& lo) {
    __nv_bfloat16 h0 = __float2bfloat16(f0);
    __nv_bfloat16 h1 = __float2bfloat16(f1);
    __nv_bfloat16 l0 = __float2bfloat16(f0 - __bfloat162float(h0));
    __nv_bfloat16 l1 = __float2bfloat16(f1 - __bfloat162float(h1));
    hi = (unsigned)__bfloat16_as_ushort(h0) | ((unsigned)__bfloat16_as_ushort(h1) << 16);
    lo = (unsigned)__bfloat16_as_ushort(l0) | ((unsigned)__bfloat16_as_ushort(l1) << 16);
}

__device__ __forceinline__ void mma16816(float* c,
    unsigned a0, unsigned a1, unsigned a2, unsigned a3,
    unsigned b0, unsigned b1)
{
    asm volatile(
        "mma.sync.aligned.m16n8k16.row.col.f32.bf16.bf16.f32 "
        "{%0,%1,%2,%3}, {%4,%5,%6,%7}, {%8,%9}, {%0,%1,%2,%3};"
        : "+f"(c[0]), "+f"(c[1]), "+f"(c[2]), "+f"(c[3])
        : "r"(a0), "r"(a1), "r"(a2), "r"(a3), "r"(b0), "r"(b1));
}

// ---------------------------------------------------------------------------
// 1) embedding gather with source reversal
// ---------------------------------------------------------------------------
__global__ void embed_rev_kernel(const int* __restrict__ x,
                                 const float* __restrict__ emb_src) {
    int bs = blockIdx.x;
    int b = bs >> 6, s = bs & 63;
    int tok = x[b*SS + (SS-1 - s)];
    const float4* src = (const float4*)(emb_src + (size_t)tok*EE);
    float4* dst = (float4*)(g_embx + (size_t)bs*EE);
    for (int i = threadIdx.x; i < EE/4; i += blockDim.x) dst[i] = src[i];
}

// ---------------------------------------------------------------------------
// 2) Split-bf16 tensor-core GEMM (TN): C[m][n] = A[m][:].W[n][:] + bias[n]
//    BM=BN=128, BK=32, 256 threads, 8 warps as 4(M)x2(N), warp tile 32x64.
//    D += Ahi*Whi + Ahi*Wlo + Alo*Whi  (f32 accum; lo*lo dropped, ~2^-32)
//    remap=1: output row r=(t*32+b) written to row (b*63+t). N%128==0, K%32==0.
// ---------------------------------------------------------------------------
__global__ __launch_bounds__(256) void bgemm128(
    const float* __restrict__ A, const float* __restrict__ W,
    const float* __restrict__ bias, float* __restrict__ C,
    int M, int N, int K, int remap)
{
    __shared__ unsigned sAh[128][17], sAl[128][17];
    __shared__ unsigned sWh[128][17], sWl[128][17];

    int tid = threadIdx.x;
    int m0 = blockIdx.x * 128;
    int n0 = blockIdx.y * 128;

    int lane = tid & 31, wid = tid >> 5;
    int wm = (wid & 3) * 32;      // warp m offset in tile
    int wn = (wid >> 2) * 64;     // warp n offset in tile
    int grp = lane >> 2, q = lane & 3;

    float c[2][8][4];
    #pragma unroll
    for (int mf = 0; mf < 2; mf++)
        #pragma unroll
        for (int nf = 0; nf < 8; nf++)
            #pragma unroll
            for (int i = 0; i < 4; i++) c[mf][nf][i] = 0.f;

    int r  = tid >> 1;            // 0..127 tile row for loads
    int kb = (tid & 1) * 16;      // float col base
    int kw = (tid & 1) * 8;       // u32 col base

    for (int k0 = 0; k0 < K; k0 += 32) {
        // load + convert A tile (guard M)
        {
            int gm = m0 + r;
            float f[16];
            if (gm < M) {
                const float4* src = (const float4*)(A + (size_t)gm*K + k0 + kb);
                float4 v0 = src[0], v1 = src[1], v2 = src[2], v3 = src[3];
                f[0]=v0.x;f[1]=v0.y;f[2]=v0.z;f[3]=v0.w;
                f[4]=v1.x;f[5]=v1.y;f[6]=v1.z;f[7]=v1.w;
                f[8]=v2.x;f[9]=v2.y;f[10]=v2.z;f[11]=v2.w;
                f[12]=v3.x;f[13]=v3.y;f[14]=v3.z;f[15]=v3.w;
            } else {
                #pragma unroll
                for (int i = 0; i < 16; i++) f[i] = 0.f;
            }
            #pragma unroll
            for (int i = 0; i < 8; i++) {
                unsigned h, l;
                cvt2(f[2*i], f[2*i+1], h, l);
                sAh[r][kw+i] = h; sAl[r][kw+i] = l;
            }
        }
        // load + convert W tile (N%128==0, no guard)
        {
            const float4* src = (const float4*)(W + (size_t)(n0+r)*K + k0 + kb);
            float4 v0 = src[0], v1 = src[1], v2 = src[2], v3 = src[3];
            float f[16];
            f[0]=v0.x;f[1]=v0.y;f[2]=v0.z;f[3]=v0.w;
            f[4]=v1.x;f[5]=v1.y;f[6]=v1.z;f[7]=v1.w;
            f[8]=v2.x;f[9]=v2.y;f[10]=v2.z;f[11]=v2.w;
            f[12]=v3.x;f[13]=v3.y;f[14]=v3.z;f[15]=v3.w;
            #pragma unroll
            for (int i = 0; i < 8; i++) {
                unsigned h, l;
                cvt2(f[2*i], f[2*i+1], h, l);
                sWh[r][kw+i] = h; sWl[r][kw+i] = l;
            }
        }
        __syncthreads();

        #pragma unroll
        for (int ks = 0; ks < 2; ks++) {
            int k8 = ks*8;
            unsigned Ah0[2], Ah1[2], Ah2[2], Ah3[2];
            unsigned Al0[2], Al1[2], Al2[2], Al3[2];
            #pragma unroll
            for (int mf = 0; mf < 2; mf++) {
                int mb = wm + mf*16;
                Ah0[mf] = sAh[mb+grp  ][k8+q];   Ah1[mf] = sAh[mb+grp+8][k8+q];
                Ah2[mf] = sAh[mb+grp  ][k8+q+4]; Ah3[mf] = sAh[mb+grp+8][k8+q+4];
                Al0[mf] = sAl[mb+grp  ][k8+q];   Al1[mf] = sAl[mb+grp+8][k8+q];
                Al2[mf] = sAl[mb+grp  ][k8+q+4]; Al3[mf] = sAl[mb+grp+8][k8+q+4];
            }
            #pragma unroll
            for (int nf = 0; nf < 8; nf++) {
                int nb = wn + nf*8;
                unsigned Bh0 = sWh[nb+grp][k8+q], Bh1 = sWh[nb+grp][k8+q+4];
                unsigned Bl0 = sWl[nb+grp][k8+q], Bl1 = sWl[nb+grp][k8+q+4];
                #pragma unroll
                for (int mf = 0; mf < 2; mf++) {
                    mma16816(c[mf][nf], Ah0[mf],Ah1[mf],Ah2[mf],Ah3[mf], Bh0,Bh1);
                    mma16816(c[mf][nf], Ah0[mf],Ah1[mf],Ah2[mf],Ah3[mf], Bl0,Bl1);
                    mma16816(c[mf][nf], Al0[mf],Al1[mf],Al2[mf],Al3[mf], Bh0,Bh1);
                }
            }
        }
        __syncthreads();
    }

    // epilogue: c0=(grp,2q) c1=(grp,2q+1) c2=(grp+8,2q) c3=(grp+8,2q+1)
    #pragma unroll
    for (int mf = 0; mf < 2; mf++) {
        #pragma unroll
        for (int nf = 0; nf < 8; nf++) {
            int gn = n0 + wn + nf*8 + q*2;
            float b0 = bias[gn], b1 = bias[gn+1];
            int gm0 = m0 + wm + mf*16 + grp;
            int gm1 = gm0 + 8;
            if (gm0 < M) {
                int row = remap ? (gm0 & 31)*63 + (gm0 >> 5) : gm0;
                C[(size_t)row*N + gn]     = c[mf][nf][0] + b0;
                C[(size_t)row*N + gn + 1] = c[mf][nf][1] + b1;
            }
            if (gm1 < M) {
                int row = remap ? (gm1 & 31)*63 + (gm1 >> 5) : gm1;
                C[(size_t)row*N + gn]     = c[mf][nf][2] + b0;
                C[(size_t)row*N + gn + 1] = c[mf][nf][3] + b1;
            }
        }
    }
}

// ---------------------------------------------------------------------------
// 3) Decoder GEMM (fp32 exact), dual-matrix (unchanged from R5)
// ---------------------------------------------------------------------------
__global__ __launch_bounds__(256) void dec_gemm(
    const float* __restrict__ A1, const float* __restrict__ W1,
    const float* __restrict__ bias, float* __restrict__ C1, int K1,
    const float* __restrict__ A2, const float* __restrict__ W2,
    float* __restrict__ C2, int K2, int N)
{
    const float* A; const float* W; const float* bs; float* C; int K;
    if (blockIdx.y == 0) { A = A1; W = W1; bs = bias;    C = C1; K = K1; }
    else                 { A = A2; W = W2; bs = nullptr; C = C2; K = K2; }

    __shared__ float As[32][34];
    __shared__ float Ws[32][33];
    int tid = threadIdx.x;
    int tx = tid & 31;
    int ty = tid >> 5;
    int n0 = blockIdx.x * 32;

    ull acc01 = 0ULL, acc23 = 0ULL;

    int arow = tid >> 3;
    int ac4  = (tid & 7) * 4;

    for (int k0 = 0; k0 < K; k0 += 32) {
        float4 va = *(const float4*)(A + (size_t)arow*K + k0 + ac4);
        As[ac4+0][arow]=va.x; As[ac4+1][arow]=va.y;
        As[ac4+2][arow]=va.z; As[ac4+3][arow]=va.w;
        float4 vw = *(const float4*)(W + (size_t)(n0+arow)*K + k0 + ac4);
        Ws[ac4+0][arow]=vw.x; Ws[ac4+1][arow]=vw.y;
        Ws[ac4+2][arow]=vw.z; Ws[ac4+3][arow]=vw.w;
        __syncthreads();
        #pragma unroll
        for (int kk = 0; kk < 32; kk++) {
            float w = Ws[kk][tx];
            ull ww; asm("mov.b64 %0, {%1, %1};" : "=l"(ww) : "f"(w));
            ull a01 = *(const ull*)&As[kk][ty*4];
            ull a23 = *(const ull*)&As[kk][ty*4+2];
            asm("fma.rn.f32x2 %0, %1, %2, %0;" : "+l"(acc01) : "l"(a01), "l"(ww));
            asm("fma.rn.f32x2 %0, %1, %2, %0;" : "+l"(acc23) : "l"(a23), "l"(ww));
        }
        __syncthreads();
    }

    float bv = bs ? bs[n0 + tx] : 0.f;
    float v0, v1, v2, v3;
    asm("mov.b64 {%0, %1}, %2;" : "=f"(v0), "=f"(v1) : "l"(acc01));
    asm("mov.b64 {%0, %1}, %2;" : "=f"(v2), "=f"(v3) : "l"(acc23));
    int b = ty*4, n = n0 + tx;
    C[(size_t)(b+0)*N + n] = v0 + bv;
    C[(size_t)(b+1)*N + n] = v1 + bv;
    C[(size_t)(b+2)*N + n] = v2 + bv;
    C[(size_t)(b+3)*N + n] = v3 + bv;
}

// ---------------------------------------------------------------------------
// 4) Encoder recurrence step (R5 version, per-step launches)
// ---------------------------------------------------------------------------
__global__ __launch_bounds__(256) void enc_step(
    const float* __restrict__ whhF, const float* __restrict__ whhB,
    int layer, int step)
{
    __shared__ float sh[256*33];
    int tid = threadIdx.x;
    int dir = blockIdx.y;
    const float* whh = dir ? whhB : whhF;
    const float* xg  = dir ? g_xgB : g_xgF;
    int pp = step & 1;
    const float* hin  = g_hbuf + (size_t)(((layer*2+dir)*2) + pp)    * (BB*HH);
    float*       hout = g_hbuf + (size_t)(((layer*2+dir)*2) + (pp^1))* (BB*HH);
    float*       cb   = g_c    + (size_t)(layer*2+dir) * (BB*HH);
    float*       outb = layer ? g_enc : g_in1;
    int s = dir ? (63 - step) : step;

    int b = tid & 31;
    int j = blockIdx.x*8 + (tid >> 5);

    float a0=0.f, a1=0.f, a2=0.f, a3=0.f;
    for (int ch = 0; ch < 2; ch++) {
        for (int i = tid; i < 256*32; i += 256) {
            int bb = i >> 8, kk = i & 255;
            sh[kk*33 + bb] = hin[bb*HH + ch*256 + kk];
        }
        __syncthreads();
        const float4* w0 = (const float4*)(whh + (size_t)(0*HH + j)*HH + ch*256);
        const float4* w1 = (const float4*)(whh + (size_t)(1*HH + j)*HH + ch*256);
        const float4* w2 = (const float4*)(whh + (size_t)(2*HH + j)*HH + ch*256);
        const float4* w3 = (const float4*)(whh + (size_t)(3*HH + j)*HH + ch*256);
        #pragma unroll 4
        for (int k4 = 0; k4 < 64; k4++) {
            float4 v0 = w0[k4], v1 = w1[k4], v2 = w2[k4], v3 = w3[k4];
            float h0 = sh[(k4*4+0)*33 + b];
            float h1 = sh[(k4*4+1)*33 + b];
            float h2 = sh[(k4*4+2)*33 + b];
            float h3 = sh[(k4*4+3)*33 + b];
            a0 += v0.x*h0 + v0.y*h1 + v0.z*h2 + v0.w*h3;
            a1 += v1.x*h0 + v1.y*h1 + v1.z*h2 + v1.w*h3;
            a2 += v2.x*h0 + v2.y*h1 + v2.z*h2 + v2.w*h3;
            a3 += v3.x*h0 + v3.y*h1 + v3.z*h2 + v3.w*h3;
        }
        __syncthreads();
    }

    size_t row = (size_t)(b*SS + s) * (4*HH);
    float gi = xg[row + 0*HH + j] + a0;
    float gf = xg[row + 1*HH + j] + a1;
    float gg = xg[row + 2*HH + j] + a2;
    float go = xg[row + 3*HH + j] + a3;
    float cc = sigf(gf)*cb[b*HH + j] + sigf(gi)*tanhf(gg);
    float hh = sigf(go)*tanhf(cc);
    cb[b*HH + j] = cc;
    hout[b*HH + j] = hh;
    outb[(size_t)(b*SS + s)*DDm + dir*HH + j] = hh;
}

// ---------------------------------------------------------------------------
// 5) Decoder initial state
// ---------------------------------------------------------------------------
__global__ void dec_init() {
    int idx = blockIdx.x*256 + threadIdx.x;
    if (idx >= BB*HH) return;
    int b = idx >> 9, j = idx & 511;
    const int NP = BB*HH;
    float h0f = g_hbuf[(size_t)((0*2+0)*2+0)*NP + idx];
    float h0b = g_hbuf[(size_t)((0*2+1)*2+0)*NP + idx];
    float h1f = g_hbuf[(size_t)((1*2+0)*2+0)*NP + idx];
    float h1b = g_hbuf[(size_t)((1*2+1)*2+0)*NP + idx];
    float c0f = g_c[(size_t)(0*2+0)*NP + idx];
    float c0b = g_c[(size_t)(0*2+1)*NP + idx];
    float c1f = g_c[(size_t)(1*2+0)*NP + idx];
    float c1b = g_c[(size_t)(1*2+1)*NP + idx];
    g_dh0[b*DDm + j]      = h0f;  g_dh0[b*DDm + HH + j] = h0b;
    g_dc0[b*DDm + j]      = c0f;  g_dc0[b*DDm + HH + j] = c0b;
    g_dh1[b*DDm + j]      = h1f;  g_dh1[b*DDm + HH + j] = h1b;
    g_dc1[b*DDm + j]      = c1f;  g_dc1[b*DDm + HH + j] = c1b;
}

// ---------------------------------------------------------------------------
// 6) attention scores
// ---------------------------------------------------------------------------
__global__ __launch_bounds__(256) void att_scores(const float* __restrict__ va) {
    __shared__ float red[256];
    int bs = blockIdx.x;
    int b = bs >> 6;
    const float* u  = g_Uenc + (size_t)bs*DDm;
    const float* qq = g_q + (size_t)b*DDm;
    int tid = threadIdx.x;
    float p = 0.f;
    for (int e = tid; e < DDm; e += 256)
        p += va[e]*tanhf(qq[e] + u[e]);
    red[tid] = p; __syncthreads();
    for (int off = 128; off > 0; off >>= 1) {
        if (tid < off) red[tid] += red[tid+off];
        __syncthreads();
    }
    if (tid == 0) g_sc[bs] = red[0];
}

// ---------------------------------------------------------------------------
// 7) softmax + context + target-embedding gather
// ---------------------------------------------------------------------------
__global__ __launch_bounds__(256) void softmax_ctx(
    const int* __restrict__ y, const float* __restrict__ emb_tgt, int t)
{
    __shared__ float w[SS];
    int b = blockIdx.x;
    int tid = threadIdx.x;
    if (tid < SS) w[tid] = g_sc[b*SS + tid];
    __syncthreads();
    if (tid == 0) {
        float mx = w[0];
        for (int s = 1; s < SS; s++) mx = fmaxf(mx, w[s]);
        float sm = 0.f;
        for (int s = 0; s < SS; s++) { w[s] = expf(w[s]-mx); sm += w[s]; }
        float inv = 1.0f/sm;
        for (int s = 0; s < SS; s++) w[s] *= inv;
    }
    __syncthreads();
    for (int d = tid; d < DDm; d += 256) {
        float acc = 0.f;
        const float* e = g_enc + (size_t)(b*SS)*DDm + d;
        #pragma unroll 4
        for (int s = 0; s < SS; s++) acc += w[s]*e[(size_t)s*DDm];
        g_xcat[(size_t)b*(EE+DDm) + EE + d] = acc;
    }
    int tok = y[b*TT + t];
    const float* es = emb_tgt + (size_t)tok*EE;
    for (int e = tid; e < EE; e += 256)
        g_xcat[(size_t)b*(EE+DDm) + e] = es[e];
}

// ---------------------------------------------------------------------------
// 8) LSTM cell pointwise: gates = gA + gB
// ---------------------------------------------------------------------------
__global__ void cell_update2(float* __restrict__ cbuf, float* __restrict__ hbuf,
                             float* __restrict__ H1, int t)
{
    int idx = blockIdx.x*256 + threadIdx.x;
    if (idx >= BB*DDm) return;
    int b = idx >> 10, j = idx & 1023;
    const float* ga = g_gA + (size_t)b*4*DDm;
    const float* gb = g_gB + (size_t)b*4*DDm;
    float gi = ga[j]         + gb[j];
    float gf = ga[DDm + j]   + gb[DDm + j];
    float gg = ga[2*DDm + j] + gb[2*DDm + j];
    float go = ga[3*DDm + j] + gb[3*DDm + j];
    float cc = sigf(gf)*cbuf[idx] + sigf(gi)*tanhf(gg);
    float hh = sigf(go)*tanhf(cc);
    cbuf[idx] = cc;
    hbuf[idx] = hh;
    if (H1) H1[((size_t)t*BB + b)*DDm + j] = hh;
}

// ---------------------------------------------------------------------------
// host driver
// ---------------------------------------------------------------------------
static float* symf(const void* s) {
    void* p = nullptr;
    cudaGetSymbolAddress(&p, s);
    return (float*)p;
}

extern "C" void kernel_launch(void* const* d_in, const int* in_sizes, int n_in,
                              void* d_out, int out_size) {
    const int*   x        = (const int*)  d_in[0];
    const int*   y        = (const int*)  d_in[1];
    const float* emb_src  = (const float*)d_in[2];
    const float* emb_tgt  = (const float*)d_in[3];
    const float* e0f_wih  = (const float*)d_in[4];
    const float* e0f_whh  = (const float*)d_in[5];
    const float* e0f_b    = (const float*)d_in[6];
    const float* e0b_wih  = (const float*)d_in[7];
    const float* e0b_whh  = (const float*)d_in[8];
    const float* e0b_b    = (const float*)d_in[9];
    const float* e1f_wih  = (const float*)d_in[10];
    const float* e1f_whh  = (const float*)d_in[11];
    const float* e1f_b    = (const float*)d_in[12];
    const float* e1b_wih  = (const float*)d_in[13];
    const float* e1b_whh  = (const float*)d_in[14];
    const float* e1b_b    = (const float*)d_in[15];
    const float* Wa_w     = (const float*)d_in[16];
    const float* Wa_b     = (const float*)d_in[17];
    const float* Ua_w     = (const float*)d_in[18];
    const float* Ua_b     = (const float*)d_in[19];
    const float* va_w     = (const float*)d_in[20];
    const float* d0_wih   = (const float*)d_in[21];
    const float* d0_whh   = (const float*)d_in[22];
    const float* d0_b     = (const float*)d_in[23];
    const float* d1_wih   = (const float*)d_in[24];
    const float* d1_whh   = (const float*)d_in[25];
    const float* d1_b     = (const float*)d_in[26];
    const float* fc_w     = (const float*)d_in[27];
    const float* fc_b     = (const float*)d_in[28];
    float* out = (float*)d_out;

    float* p_embx = symf(g_embx);
    float* p_xgF  = symf(g_xgF);
    float* p_xgB  = symf(g_xgB);
    float* p_in1  = symf(g_in1);
    float* p_enc  = symf(g_enc);
    float* p_Uenc = symf(g_Uenc);
    float* p_hbuf = symf(g_hbuf);
    float* p_c    = symf(g_c);
    float* p_dh0  = symf(g_dh0);
    float* p_dh1  = symf(g_dh1);
    float* p_q    = symf(g_q);
    float* p_xcat = symf(g_xcat);
    float* p_gA   = symf(g_gA);
    float* p_gB   = symf(g_gB);
    float* p_dc0  = symf(g_dc0);
    float* p_dc1  = symf(g_dc1);
    float* p_H1   = symf(g_H1);

    const int M  = BB*SS;     // 2048

    // 1) embedding + reverse
    embed_rev_kernel<<<BB*SS, 128>>>(x, emb_src);

    // 2) layer-0 input GEMMs (tensor core, split-bf16)
    {
        dim3 grid(M/128, (4*HH)/128);
        bgemm128<<<grid, 256>>>(p_embx, e0f_wih, e0f_b, p_xgF, M, 4*HH, EE, 0);
        bgemm128<<<grid, 256>>>(p_embx, e0b_wih, e0b_b, p_xgB, M, 4*HH, EE, 0);
    }

    cudaMemsetAsync(p_hbuf, 0, sizeof(float)*2*2*2*BB*HH);
    cudaMemsetAsync(p_c,    0, sizeof(float)*2*2*BB*HH);

    // 3) layer-0 recurrence
    {
        dim3 grid(HH/8, 2);
        for (int s = 0; s < SS; s++)
            enc_step<<<grid, 256>>>(e0f_whh, e0b_whh, 0, s);
    }

    // 4) layer-1 input GEMMs
    {
        dim3 grid(M/128, (4*HH)/128);
        bgemm128<<<grid, 256>>>(p_in1, e1f_wih, e1f_b, p_xgF, M, 4*HH, DDm, 0);
        bgemm128<<<grid, 256>>>(p_in1, e1b_wih, e1b_b, p_xgB, M, 4*HH, DDm, 0);
    }

    // 5) layer-1 recurrence
    {
        dim3 grid(HH/8, 2);
        for (int s = 0; s < SS; s++)
            enc_step<<<grid, 256>>>(e1f_whh, e1b_whh, 1, s);
    }

    // 6) Uenc = enc @ Ua^T + Ua_b
    {
        dim3 grid(M/128, DDm/128);
        bgemm128<<<grid, 256>>>(p_enc, Ua_w, Ua_b, p_Uenc, M, DDm, DDm, 0);
    }

    // 7) decoder initial state
    dec_init<<<(BB*HH + 255)/256, 256>>>();

    // 8) decoder steps (7 launches per step; exact fp32)
    for (int t = 0; t < TT-1; t++) {
        dec_gemm<<<dim3(DDm/32, 1), 256>>>(p_dh1, Wa_w, Wa_b, p_q, DDm,
                                           nullptr, nullptr, nullptr, 32, DDm);
        att_scores<<<BB*SS, 256>>>(va_w);
        softmax_ctx<<<BB, 256>>>(y, emb_tgt, t);
        dec_gemm<<<dim3((4*DDm)/32, 2), 256>>>(p_xcat, d0_wih, d0_b, p_gA, EE+DDm,
                                               p_dh0, d0_whh, p_gB, DDm, 4*DDm);
        cell_update2<<<(BB*DDm + 255)/256, 256>>>(p_dc0, p_dh0, nullptr, t);
        dec_gemm<<<dim3((4*DDm)/32, 2), 256>>>(p_dh0, d1_wih, d1_b, p_gA, DDm,
                                               p_dh1, d1_whh, p_gB, DDm, 4*DDm);
        cell_update2<<<(BB*DDm + 255)/256, 256>>>(p_dc1, p_dh1, p_H1, t);
    }

    // 9) deferred logits GEMM (tensor core, split-bf16, remapped rows)
    {
        int Mf = 63*BB;   // 2016
        dim3 grid((Mf + 127)/128, VV/128);
        bgemm128<<<grid, 256>>>(p_H1, fc_w, fc_b, out, Mf, VV, DDm, 1);
    }
}

// round 9
// speedup vs baseline: 3.0679x; 1.3927x over previous
#include <cuda_runtime.h>
#include <cuda_bf16.h>
#include <math.h>

// Problem constants
#define BB   32      // batch
#define SS   64      // src len
#define TT   64      // tgt len (63 decode steps)
#define EE   512     // embed dim
#define HH   512     // encoder hidden per dir
#define DDm  1024    // 2*H
#define VV   32000   // vocab

// ---------------------------------------------------------------------------
// Static device scratch
// ---------------------------------------------------------------------------
__device__ __align__(16) float g_embx [BB*SS*EE];
__device__ __align__(16) float g_xgF  [BB*SS*4*HH];
__device__ __align__(16) float g_xgB  [BB*SS*4*HH];
__device__ __align__(16) float g_in1  [BB*SS*DDm];
__device__ __align__(16) float g_enc  [BB*SS*DDm];
__device__ __align__(16) float g_Uenc [BB*SS*DDm];
__device__ __align__(16) float g_hbuf [2*2*2*BB*HH];   // [layer][dir][pp][b*HH+j]
__device__ __align__(16) float g_c    [2*2*BB*HH];
__device__ __align__(16) float g_dh0  [2*BB*DDm];      // ping-pong
__device__ __align__(16) float g_dc0  [BB*DDm];
__device__ __align__(16) float g_dh1  [2*BB*DDm];      // ping-pong
__device__ __align__(16) float g_dc1  [BB*DDm];
__device__ __align__(16) float g_q    [BB*DDm];
__device__ __align__(16) float g_sc   [BB*SS];
__device__ __align__(16) float g_xcat [BB*(EE+DDm)];
__device__ __align__(16) float g_H1   [63*BB*DDm];

// converted-weight pool (u32 = packed bf16 pair; interleaved [hiPair, loPair])
#define OFF_E0F_WIH 0ull
#define OFF_E0B_WIH (OFF_E0F_WIH + 2048ull*512)
#define OFF_E1F_WIH (OFF_E0B_WIH + 2048ull*512)
#define OFF_E1B_WIH (OFF_E1F_WIH + 2048ull*1024)
#define OFF_E0F_WHH (OFF_E1B_WIH + 2048ull*1024)
#define OFF_E0B_WHH (OFF_E0F_WHH + 2048ull*512)
#define OFF_E1F_WHH (OFF_E0B_WHH + 2048ull*512)
#define OFF_E1B_WHH (OFF_E1F_WHH + 2048ull*512)
#define OFF_UA      (OFF_E1B_WHH + 2048ull*512)
#define OFF_WA      (OFF_UA + 1024ull*1024)
#define OFF_D0WIH   (OFF_WA + 1024ull*1024)
#define OFF_D0WHH   (OFF_D0WIH + 4096ull*1536)
#define OFF_D1WIH   (OFF_D0WHH + 4096ull*1024)
#define OFF_D1WHH   (OFF_D1WIH + 4096ull*1024)
#define OFF_FC      (OFF_D1WHH + 4096ull*1024)
#define WCVT_TOTAL  (OFF_FC + 32000ull*1024)
__device__ __align__(16) unsigned g_wcvt[WCVT_TOTAL];

__device__ __forceinline__ float sigf(float v) { return 1.0f/(1.0f + expf(-v)); }

// fp32 pair -> packed (bf16 hi, bf16 lo)
__device__ __forceinline__ void cvt2(float f0, float f1, unsigned& hi, unsigned& lo) {
    __nv_bfloat16 h0 = __float2bfloat16(f0);
    __nv_bfloat16 h1 = __float2bfloat16(f1);
    __nv_bfloat16 l0 = __float2bfloat16(f0 - __bfloat162float(h0));
    __nv_bfloat16 l1 = __float2bfloat16(f1 - __bfloat162float(h1));
    hi = (unsigned)__bfloat16_as_ushort(h0) | ((unsigned)__bfloat16_as_ushort(h1) << 16);
    lo = (unsigned)__bfloat16_as_ushort(l0) | ((unsigned)__bfloat16_as_ushort(l1) << 16);
}

__device__ __forceinline__ void mma16816(float* c,
    unsigned a0, unsigned a1, unsigned a2, unsigned a3,
    unsigned b0, unsigned b1)
{
    asm volatile(
        "mma.sync.aligned.m16n8k16.row.col.f32.bf16.bf16.f32 "
        "{%0,%1,%2,%3}, {%4,%5,%6,%7}, {%8,%9}, {%0,%1,%2,%3};"
        : "+f"(c[0]), "+f"(c[1]), "+f"(c[2]), "+f"(c[3])
        : "r"(a0), "r"(a1), "r"(a2), "r"(a3), "r"(b0), "r"(b1));
}

// ---------------------------------------------------------------------------
// weight conversion: fp32 -> interleaved (hiPair, loPair) u32
// ---------------------------------------------------------------------------
__global__ void cvtW(const float* __restrict__ src, unsigned* __restrict__ dst, int np) {
    for (int p = blockIdx.x*blockDim.x + threadIdx.x; p < np; p += gridDim.x*blockDim.x) {
        unsigned h, l;
        cvt2(src[2*p], src[2*p+1], h, l);
        dst[2*p] = h; dst[2*p+1] = l;
    }
}

// ---------------------------------------------------------------------------
// embedding gather with source reversal
// ---------------------------------------------------------------------------
__global__ void embed_rev_kernel(const int* __restrict__ x,
                                 const float* __restrict__ emb_src) {
    int bs = blockIdx.x;
    int b = bs >> 6, s = bs & 63;
    int tok = x[b*SS + (SS-1 - s)];
    const float4* src = (const float4*)(emb_src + (size_t)tok*EE);
    float4* dst = (float4*)(g_embx + (size_t)bs*EE);
    for (int i = threadIdx.x; i < EE/4; i += blockDim.x) dst[i] = src[i];
}

// ---------------------------------------------------------------------------
// bgemm128: split-bf16 mma GEMM, BM=BN=128, BK=32. A fp32 (converted
// in-kernel), W pre-converted. remap=1: row (t*32+b) -> (b*63+t).
// ---------------------------------------------------------------------------
__global__ __launch_bounds__(256) void bgemm128(
    const float* __restrict__ A, const unsigned* __restrict__ Whl,
    const float* __restrict__ bias, float* __restrict__ C,
    int M, int N, int K, int remap)
{
    __shared__ unsigned sAh[128][17], sAl[128][17];
    __shared__ unsigned sWh[128][17], sWl[128][17];

    int tid = threadIdx.x;
    int m0 = blockIdx.x * 128;
    int n0 = blockIdx.y * 128;

    int lane = tid & 31, wid = tid >> 5;
    int wm = (wid & 3) * 32;
    int wn = (wid >> 2) * 64;
    int grp = lane >> 2, q = lane & 3;

    float c[2][8][4];
    #pragma unroll
    for (int mf = 0; mf < 2; mf++)
        #pragma unroll
        for (int nf = 0; nf < 8; nf++)
            #pragma unroll
            for (int i = 0; i < 4; i++) c[mf][nf][i] = 0.f;

    int r  = tid >> 1;
    int kb = (tid & 1) * 16;   // float col base
    int kw = (tid & 1) * 8;    // u32 col base

    for (int k0 = 0; k0 < K; k0 += 32) {
        // A tile (guard M), convert fp32 -> split bf16
        {
            int gm = m0 + r;
            float f[16];
            if (gm < M) {
                const float4* src = (const float4*)(A + (size_t)gm*K + k0 + kb);
                float4 v0 = src[0], v1 = src[1], v2 = src[2], v3 = src[3];
                f[0]=v0.x;f[1]=v0.y;f[2]=v0.z;f[3]=v0.w;
                f[4]=v1.x;f[5]=v1.y;f[6]=v1.z;f[7]=v1.w;
                f[8]=v2.x;f[9]=v2.y;f[10]=v2.z;f[11]=v2.w;
                f[12]=v3.x;f[13]=v3.y;f[14]=v3.z;f[15]=v3.w;
            } else {
                #pragma unroll
                for (int i = 0; i < 16; i++) f[i] = 0.f;
            }
            #pragma unroll
            for (int i = 0; i < 8; i++) {
                unsigned h, l;
                cvt2(f[2*i], f[2*i+1], h, l);
                sAh[r][kw+i] = h; sAl[r][kw+i] = l;
            }
        }
        // W tile (pre-converted, N%128==0)
        {
            const unsigned* wr = Whl + (size_t)(n0+r)*K + k0 + kb;
            #pragma unroll
            for (int i = 0; i < 4; i++) {
                uint4 v = *(const uint4*)(wr + i*4);
                int cw = kw + i*2;
                sWh[r][cw] = v.x;   sWl[r][cw] = v.y;
                sWh[r][cw+1] = v.z; sWl[r][cw+1] = v.w;
            }
        }
        __syncthreads();

        #pragma unroll
        for (int ks = 0; ks < 2; ks++) {
            int k8 = ks*8;
            unsigned Ah0[2], Ah1[2], Ah2[2], Ah3[2];
            unsigned Al0[2], Al1[2], Al2[2], Al3[2];
            #pragma unroll
            for (int mf = 0; mf < 2; mf++) {
                int mb = wm + mf*16;
                Ah0[mf] = sAh[mb+grp  ][k8+q];   Ah1[mf] = sAh[mb+grp+8][k8+q];
                Ah2[mf] = sAh[mb+grp  ][k8+q+4]; Ah3[mf] = sAh[mb+grp+8][k8+q+4];
                Al0[mf] = sAl[mb+grp  ][k8+q];   Al1[mf] = sAl[mb+grp+8][k8+q];
                Al2[mf] = sAl[mb+grp  ][k8+q+4]; Al3[mf] = sAl[mb+grp+8][k8+q+4];
            }
            #pragma unroll
            for (int nf = 0; nf < 8; nf++) {
                int nb = wn + nf*8;
                unsigned Bh0 = sWh[nb+grp][k8+q], Bh1 = sWh[nb+grp][k8+q+4];
                unsigned Bl0 = sWl[nb+grp][k8+q], Bl1 = sWl[nb+grp][k8+q+4];
                #pragma unroll
                for (int mf = 0; mf < 2; mf++) {
                    mma16816(c[mf][nf], Ah0[mf],Ah1[mf],Ah2[mf],Ah3[mf], Bh0,Bh1);
                    mma16816(c[mf][nf], Ah0[mf],Ah1[mf],Ah2[mf],Ah3[mf], Bl0,Bl1);
                    mma16816(c[mf][nf], Al0[mf],Al1[mf],Al2[mf],Al3[mf], Bh0,Bh1);
                }
            }
        }
        __syncthreads();
    }

    #pragma unroll
    for (int mf = 0; mf < 2; mf++) {
        #pragma unroll
        for (int nf = 0; nf < 8; nf++) {
            int gn = n0 + wn + nf*8 + q*2;
            float b0 = bias[gn], b1 = bias[gn+1];
            int gm0 = m0 + wm + mf*16 + grp;
            int gm1 = gm0 + 8;
            if (gm0 < M) {
                int row = remap ? (gm0 & 31)*63 + (gm0 >> 5) : gm0;
                C[(size_t)row*N + gn]     = c[mf][nf][0] + b0;
                C[(size_t)row*N + gn + 1] = c[mf][nf][1] + b1;
            }
            if (gm1 < M) {
                int row = remap ? (gm1 & 31)*63 + (gm1 >> 5) : gm1;
                C[(size_t)row*N + gn]     = c[mf][nf][2] + b0;
                C[(size_t)row*N + gn + 1] = c[mf][nf][3] + b1;
            }
        }
    }
}

// ---------------------------------------------------------------------------
// BM=32 K-loop (BK=128, register prefetch). A fp32 (cvt in-kernel),
// W pre-converted. Warp layout: mh = wid&1 (m16), wn = wid>>1 (n8).
// ---------------------------------------------------------------------------
__device__ __forceinline__ void kloop128(
    const float* __restrict__ Arow, const unsigned* __restrict__ Wrow, int K,
    unsigned (*sAh)[65], unsigned (*sAl)[65],
    unsigned (*sWh)[65], unsigned (*sWl)[65],
    float* cacc, int r, int c8, int mh, int wn, int grp, int qq)
{
    float4 fa[4]; uint4 uw[4];
    #pragma unroll
    for (int i = 0; i < 4; i++) {
        fa[i] = *(const float4*)(Arow + (c8 + i*8)*4);
        uw[i] = *(const uint4*)(Wrow + (c8 + i*8)*4);
    }
    for (int k0 = 0; k0 < K; k0 += 128) {
        __syncthreads();
        #pragma unroll
        for (int i = 0; i < 4; i++) {
            int col = (c8 + i*8)*2;
            unsigned h0,l0,h1,l1;
            cvt2(fa[i].x, fa[i].y, h0, l0);
            cvt2(fa[i].z, fa[i].w, h1, l1);
            sAh[r][col]=h0; sAl[r][col]=l0; sAh[r][col+1]=h1; sAl[r][col+1]=l1;
            sWh[r][col]=uw[i].x; sWl[r][col]=uw[i].y;
            sWh[r][col+1]=uw[i].z; sWl[r][col+1]=uw[i].w;
        }
        __syncthreads();
        if (k0 + 128 < K) {
            #pragma unroll
            for (int i = 0; i < 4; i++) {
                fa[i] = *(const float4*)(Arow + k0 + 128 + (c8 + i*8)*4);
                uw[i] = *(const uint4*)(Wrow + k0 + 128 + (c8 + i*8)*4);
            }
        }
        #pragma unroll
        for (int ks = 0; ks < 8; ks++) {
            int k8 = ks*8;
            int mb = mh*16;
            unsigned Ah0 = sAh[mb+grp  ][k8+qq],  Ah1 = sAh[mb+grp+8][k8+qq];
            unsigned Ah2 = sAh[mb+grp  ][k8+qq+4],Ah3 = sAh[mb+grp+8][k8+qq+4];
            unsigned Al0 = sAl[mb+grp  ][k8+qq],  Al1 = sAl[mb+grp+8][k8+qq];
            unsigned Al2 = sAl[mb+grp  ][k8+qq+4],Al3 = sAl[mb+grp+8][k8+qq+4];
            unsigned Bh0 = sWh[wn*8+grp][k8+qq],  Bh1 = sWh[wn*8+grp][k8+qq+4];
            unsigned Bl0 = sWl[wn*8+grp][k8+qq],  Bl1 = sWl[wn*8+grp][k8+qq+4];
            mma16816(cacc, Ah0,Ah1,Ah2,Ah3, Bh0,Bh1);
            mma16816(cacc, Ah0,Ah1,Ah2,Ah3, Bl0,Bl1);
            mma16816(cacc, Al0,Al1,Al2,Al3, Bh0,Bh1);
        }
    }
}

// ---------------------------------------------------------------------------
// cell32: fused gates-GEMM + LSTM cell. Block handles 8 j x 4 gates x 32 b.
// W row = gate*NH + j0 + jj. Two K-segments into the same accumulators.
// grid.y selects arg set (encoder fwd/bwd).
// ---------------------------------------------------------------------------
struct CArg {
    const float* A1; const unsigned* W1; int K1;
    const float* A2; const unsigned* W2; int K2;
    int NH;
    const float* gadd; int gaddB;   // gate add: [b*gaddB + gate*NH + j]
    float* cst;                     // c state, RMW [b*NH + j]
    float* hout;                    // [b*NH + j]
    float* out2; int out2B;         // optional extra h copy [b*out2B + j]
};

__global__ __launch_bounds__(256) void cell32(CArg pa, CArg pb) {
    const CArg p = blockIdx.y ? pb : pa;
    __shared__ unsigned sAh[32][65], sAl[32][65], sWh[32][65], sWl[32][65];
    int tid = threadIdx.x;
    int r = tid >> 3, c8 = tid & 7;
    int lane = tid & 31, wid = tid >> 5;
    int mh = wid & 1, wn = wid >> 1, grp = lane >> 2, qq = lane & 3;
    int j0 = blockIdx.x * 8;
    size_t wrow = (size_t)(r >> 3)*p.NH + j0 + (r & 7);

    float cacc[4] = {0.f, 0.f, 0.f, 0.f};
    kloop128(p.A1 + (size_t)r*p.K1, p.W1 + wrow*p.K1, p.K1,
             sAh, sAl, sWh, sWl, cacc, r, c8, mh, wn, grp, qq);
    if (p.K2)
        kloop128(p.A2 + (size_t)r*p.K2, p.W2 + wrow*p.K2, p.K2,
                 sAh, sAl, sWh, sWl, cacc, r, c8, mh, wn, grp, qq);

    // epilogue: frags -> smem, then fused cell update
    __syncthreads();
    float (*gsm)[33] = (float(*)[33])&sAh[0][0];
    int n = wn*8 + 2*qq;
    int b0 = mh*16 + grp;
    gsm[b0][n]   = cacc[0]; gsm[b0][n+1]   = cacc[1];
    gsm[b0+8][n] = cacc[2]; gsm[b0+8][n+1] = cacc[3];
    __syncthreads();

    int b = tid & 31, jj = tid >> 5, j = j0 + jj;
    size_t gb = (size_t)b * p.gaddB;
    float gi = gsm[b][jj]      + p.gadd[gb + 0*p.NH + j];
    float gf = gsm[b][8+jj]    + p.gadd[gb + 1*p.NH + j];
    float gg = gsm[b][16+jj]   + p.gadd[gb + 2*p.NH + j];
    float go = gsm[b][24+jj]   + p.gadd[gb + 3*p.NH + j];
    int ci = b*p.NH + j;
    float cc = sigf(gf)*p.cst[ci] + sigf(gi)*tanhf(gg);
    p.cst[ci] = cc;
    float hh = sigf(go)*tanhf(cc);
    p.hout[ci] = hh;
    if (p.out2) p.out2[(size_t)b*p.out2B + j] = hh;
}

// ---------------------------------------------------------------------------
// qgemm32: plain BM=32 GEMM (q = h1 @ Wa^T + bias). grid.x = N/32.
// ---------------------------------------------------------------------------
__global__ __launch_bounds__(256) void qgemm32(
    const float* __restrict__ A, const unsigned* __restrict__ W,
    const float* __restrict__ bias, float* __restrict__ C, int K, int N)
{
    __shared__ unsigned sAh[32][65], sAl[32][65], sWh[32][65], sWl[32][65];
    int tid = threadIdx.x;
    int r = tid >> 3, c8 = tid & 7;
    int lane = tid & 31, wid = tid >> 5;
    int mh = wid & 1, wn = wid >> 1, grp = lane >> 2, qq = lane & 3;
    int n0 = blockIdx.x * 32;

    float cacc[4] = {0.f, 0.f, 0.f, 0.f};
    kloop128(A + (size_t)r*K, W + (size_t)(n0 + r)*K, K,
             sAh, sAl, sWh, sWl, cacc, r, c8, mh, wn, grp, qq);

    int gn = n0 + wn*8 + 2*qq;
    int b0 = mh*16 + grp;
    C[(size_t)b0*N + gn]       = cacc[0] + bias[gn];
    C[(size_t)b0*N + gn + 1]   = cacc[1] + bias[gn+1];
    C[(size_t)(b0+8)*N + gn]   = cacc[2] + bias[gn];
    C[(size_t)(b0+8)*N + gn+1] = cacc[3] + bias[gn+1];
}

// ---------------------------------------------------------------------------
// decoder initial state (reads pp=0 slot of hbuf; writes slot-0 of dh0/dh1)
// ---------------------------------------------------------------------------
__global__ void dec_init() {
    int idx = blockIdx.x*256 + threadIdx.x;
    if (idx >= BB*HH) return;
    int b = idx >> 9, j = idx & 511;
    const int NP = BB*HH;
    float h0f = g_hbuf[(size_t)((0*2+0)*2+0)*NP + idx];
    float h0b = g_hbuf[(size_t)((0*2+1)*2+0)*NP + idx];
    float h1f = g_hbuf[(size_t)((1*2+0)*2+0)*NP + idx];
    float h1b = g_hbuf[(size_t)((1*2+1)*2+0)*NP + idx];
    float c0f = g_c[(size_t)(0*2+0)*NP + idx];
    float c0b = g_c[(size_t)(0*2+1)*NP + idx];
    float c1f = g_c[(size_t)(1*2+0)*NP + idx];
    float c1b = g_c[(size_t)(1*2+1)*NP + idx];
    g_dh0[b*DDm + j]      = h0f;  g_dh0[b*DDm + HH + j] = h0b;
    g_dc0[b*DDm + j]      = c0f;  g_dc0[b*DDm + HH + j] = c0b;
    g_dh1[b*DDm + j]      = h1f;  g_dh1[b*DDm + HH + j] = h1b;
    g_dc1[b*DDm + j]      = c1f;  g_dc1[b*DDm + HH + j] = c1b;
}

// ---------------------------------------------------------------------------
// attention scores: warp per (b,s). grid 256 blocks x 8 warps = 2048 rows.
// ---------------------------------------------------------------------------
__global__ __launch_bounds__(256) void att_scores2(const float* __restrict__ va) {
    int lane = threadIdx.x & 31, w = threadIdx.x >> 5;
    int task = blockIdx.x*8 + w;
    int b = task >> 6;
    const float* u  = g_Uenc + (size_t)task*DDm;
    const float* qq = g_q + (size_t)b*DDm;
    float p = 0.f;
    #pragma unroll 8
    for (int e = lane; e < DDm; e += 32)
        p += va[e]*tanhf(qq[e] + u[e]);
    #pragma unroll
    for (int off = 16; off; off >>= 1)
        p += __shfl_xor_sync(0xffffffffu, p, off);
    if (lane == 0) g_sc[task] = p;
}

// ---------------------------------------------------------------------------
// softmax + context + target-embedding gather -> g_xcat[32][1536]
// ---------------------------------------------------------------------------
__global__ __launch_bounds__(256) void softmax_ctx(
    const int* __restrict__ y, const float* __restrict__ emb_tgt, int t)
{
    __shared__ float w[SS];
    int b = blockIdx.x;
    int tid = threadIdx.x;
    if (tid < SS) w[tid] = g_sc[b*SS + tid];
    __syncthreads();
    if (tid == 0) {
        float mx = w[0];
        for (int s = 1; s < SS; s++) mx = fmaxf(mx, w[s]);
        float sm = 0.f;
        for (int s = 0; s < SS; s++) { w[s] = expf(w[s]-mx); sm += w[s]; }
        float inv = 1.0f/sm;
        for (int s = 0; s < SS; s++) w[s] *= inv;
    }
    __syncthreads();
    for (int d = tid; d < DDm; d += 256) {
        float acc = 0.f;
        const float* e = g_enc + (size_t)(b*SS)*DDm + d;
        #pragma unroll 8
        for (int s = 0; s < SS; s++) acc += w[s]*e[(size_t)s*DDm];
        g_xcat[(size_t)b*(EE+DDm) + EE + d] = acc;
    }
    int tok = y[b*TT + t];
    const float* es = emb_tgt + (size_t)tok*EE;
    for (int e = tid; e < EE; e += 256)
        g_xcat[(size_t)b*(EE+DDm) + e] = es[e];
}

// ---------------------------------------------------------------------------
// host driver
// ---------------------------------------------------------------------------
static float* symf(const void* s) {
    void* p = nullptr;
    cudaGetSymbolAddress(&p, s);
    return (float*)p;
}

extern "C" void kernel_launch(void* const* d_in, const int* in_sizes, int n_in,
                              void* d_out, int out_size) {
    const int*   x        = (const int*)  d_in[0];
    const int*   y        = (const int*)  d_in[1];
    const float* emb_src  = (const float*)d_in[2];
    const float* emb_tgt  = (const float*)d_in[3];
    const float* e0f_wih  = (const float*)d_in[4];
    const float* e0f_whh  = (const float*)d_in[5];
    const float* e0f_b    = (const float*)d_in[6];
    const float* e0b_wih  = (const float*)d_in[7];
    const float* e0b_whh  = (const float*)d_in[8];
    const float* e0b_b    = (const float*)d_in[9];
    const float* e1f_wih  = (const float*)d_in[10];
    const float* e1f_whh  = (const float*)d_in[11];
    const float* e1f_b    = (const float*)d_in[12];
    const float* e1b_wih  = (const float*)d_in[13];
    const float* e1b_whh  = (const float*)d_in[14];
    const float* e1b_b    = (const float*)d_in[15];
    const float* Wa_w     = (const float*)d_in[16];
    const float* Wa_b     = (const float*)d_in[17];
    const float* Ua_w     = (const float*)d_in[18];
    const float* Ua_b     = (const float*)d_in[19];
    const float* va_w     = (const float*)d_in[20];
    const float* d0_wih   = (const float*)d_in[21];
    const float* d0_whh   = (const float*)d_in[22];
    const float* d0_b     = (const float*)d_in[23];
    const float* d1_wih   = (const float*)d_in[24];
    const float* d1_whh   = (const float*)d_in[25];
    const float* d1_b     = (const float*)d_in[26];
    const float* fc_w     = (const float*)d_in[27];
    const float* fc_b     = (const float*)d_in[28];
    float* out = (float*)d_out;

    float* p_embx = symf(g_embx);
    float* p_xgF  = symf(g_xgF);
    float* p_xgB  = symf(g_xgB);
    float* p_in1  = symf(g_in1);
    float* p_enc  = symf(g_enc);
    float* p_Uenc = symf(g_Uenc);
    float* p_hbuf = symf(g_hbuf);
    float* p_c    = symf(g_c);
    float* p_dh0  = symf(g_dh0);
    float* p_dc0  = symf(g_dc0);
    float* p_dh1  = symf(g_dh1);
    float* p_dc1  = symf(g_dc1);
    float* p_q    = symf(g_q);
    float* p_xcat = symf(g_xcat);
    float* p_H1   = symf(g_H1);
    unsigned* p_w = (unsigned*)symf(g_wcvt);

    const int M = BB*SS;   // 2048

    // 0) convert all weights to split-bf16 pairs
    {
        struct { const float* s; size_t off; size_t n; } cv[15] = {
            { e0f_wih, OFF_E0F_WIH, 2048ull*512  },
            { e0b_wih, OFF_E0B_WIH, 2048ull*512  },
            { e1f_wih, OFF_E1F_WIH, 2048ull*1024 },
            { e1b_wih, OFF_E1B_WIH, 2048ull*1024 },
            { e0f_whh, OFF_E0F_WHH, 2048ull*512  },
            { e0b_whh, OFF_E0B_WHH, 2048ull*512  },
            { e1f_whh, OFF_E1F_WHH, 2048ull*512  },
            { e1b_whh, OFF_E1B_WHH, 2048ull*512  },
            { Ua_w,    OFF_UA,      1024ull*1024 },
            { Wa_w,    OFF_WA,      1024ull*1024 },
            { d0_wih,  OFF_D0WIH,   4096ull*1536 },
            { d0_whh,  OFF_D0WHH,   4096ull*1024 },
            { d1_wih,  OFF_D1WIH,   4096ull*1024 },
            { d1_whh,  OFF_D1WHH,   4096ull*1024 },
            { fc_w,    OFF_FC,      32000ull*1024 },
        };
        for (int i = 0; i < 15; i++)
            cvtW<<<256, 256>>>(cv[i].s, p_w + cv[i].off, (int)(cv[i].n/2));
    }

    // 1) embedding + reverse
    embed_rev_kernel<<<BB*SS, 128>>>(x, emb_src);

    // 2) layer-0 input GEMMs
    {
        dim3 grid(M/128, (4*HH)/128);
        bgemm128<<<grid, 256>>>(p_embx, p_w + OFF_E0F_WIH, e0f_b, p_xgF, M, 4*HH, EE, 0);
        bgemm128<<<grid, 256>>>(p_embx, p_w + OFF_E0B_WIH, e0b_b, p_xgB, M, 4*HH, EE, 0);
    }

    cudaMemsetAsync(p_hbuf, 0, sizeof(float)*2*2*2*BB*HH);
    cudaMemsetAsync(p_c,    0, sizeof(float)*2*2*BB*HH);

    // 3+5) encoder recurrences (fused gates+cell, both dirs per launch)
    const size_t whhOff[2][2] = { {OFF_E0F_WHH, OFF_E0B_WHH}, {OFF_E1F_WHH, OFF_E1B_WHH} };
    for (int layer = 0; layer < 2; layer++) {
        if (layer == 1) {
            dim3 grid(M/128, (4*HH)/128);
            bgemm128<<<grid, 256>>>(p_in1, p_w + OFF_E1F_WIH, e1f_b, p_xgF, M, 4*HH, DDm, 0);
            bgemm128<<<grid, 256>>>(p_in1, p_w + OFF_E1B_WIH, e1b_b, p_xgB, M, 4*HH, DDm, 0);
        }
        float* outb = layer ? p_enc : p_in1;
        for (int s = 0; s < SS; s++) {
            int pp = s & 1;
            CArg a{}, bg{};
            // dir 0 (forward), time index s
            a.A1 = p_hbuf + (size_t)((layer*2+0)*2 + pp)*(BB*HH);
            a.W1 = p_w + whhOff[layer][0]; a.K1 = HH;
            a.A2 = nullptr; a.W2 = nullptr; a.K2 = 0;
            a.NH = HH;
            a.gadd = p_xgF + (size_t)s*4*HH;  a.gaddB = SS*4*HH;
            a.cst  = p_c + (size_t)(layer*2+0)*(BB*HH);
            a.hout = p_hbuf + (size_t)((layer*2+0)*2 + (pp^1))*(BB*HH);
            a.out2 = outb + (size_t)s*DDm;    a.out2B = SS*DDm;
            // dir 1 (backward), time index 63-s
            int s1 = 63 - s;
            bg.A1 = p_hbuf + (size_t)((layer*2+1)*2 + pp)*(BB*HH);
            bg.W1 = p_w + whhOff[layer][1]; bg.K1 = HH;
            bg.A2 = nullptr; bg.W2 = nullptr; bg.K2 = 0;
            bg.NH = HH;
            bg.gadd = p_xgB + (size_t)s1*4*HH; bg.gaddB = SS*4*HH;
            bg.cst  = p_c + (size_t)(layer*2+1)*(BB*HH);
            bg.hout = p_hbuf + (size_t)((layer*2+1)*2 + (pp^1))*(BB*HH);
            bg.out2 = outb + (size_t)s1*DDm + HH; bg.out2B = SS*DDm;
            cell32<<<dim3(HH/8, 2), 256>>>(a, bg);
        }
    }

    // 6) Uenc = enc @ Ua^T + Ua_b
    {
        dim3 grid(M/128, DDm/128);
        bgemm128<<<grid, 256>>>(p_enc, p_w + OFF_UA, Ua_b, p_Uenc, M, DDm, DDm, 0);
    }

    // 7) decoder initial state
    dec_init<<<(BB*HH + 255)/256, 256>>>();

    // 8) decoder steps (5 launches per step)
    for (int t = 0; t < TT-1; t++) {
        int pp = t & 1;
        float* h0r = p_dh0 + (size_t)pp*(BB*DDm);
        float* h0w = p_dh0 + (size_t)(pp^1)*(BB*DDm);
        float* h1r = p_dh1 + (size_t)pp*(BB*DDm);
        float* h1w = p_dh1 + (size_t)(pp^1)*(BB*DDm);

        qgemm32<<<DDm/32, 256>>>(h1r, p_w + OFF_WA, Wa_b, p_q, DDm, DDm);
        att_scores2<<<256, 256>>>(va_w);
        softmax_ctx<<<BB, 256>>>(y, emb_tgt, t);

        CArg c0{};
        c0.A1 = p_xcat; c0.W1 = p_w + OFF_D0WIH; c0.K1 = EE+DDm;
        c0.A2 = h0r;    c0.W2 = p_w + OFF_D0WHH; c0.K2 = DDm;
        c0.NH = DDm; c0.gadd = d0_b; c0.gaddB = 0;
        c0.cst = p_dc0; c0.hout = h0w; c0.out2 = nullptr; c0.out2B = 0;
        cell32<<<dim3(DDm/8, 1), 256>>>(c0, c0);

        CArg c1{};
        c1.A1 = h0w; c1.W1 = p_w + OFF_D1WIH; c1.K1 = DDm;
        c1.A2 = h1r; c1.W2 = p_w + OFF_D1WHH; c1.K2 = DDm;
        c1.NH = DDm; c1.gadd = d1_b; c1.gaddB = 0;
        c1.cst = p_dc1; c1.hout = h1w;
        c1.out2 = p_H1 + (size_t)t*BB*DDm; c1.out2B = DDm;
        cell32<<<dim3(DDm/8, 1), 256>>>(c1, c1);
    }

    // 9) deferred logits GEMM
    {
        int Mf = 63*BB;   // 2016
        dim3 grid((Mf + 127)/128, VV/128);
        bgemm128<<<grid, 256>>>(p_H1, p_w + OFF_FC, fc_b, out, Mf, VV, DDm, 1);
    }
}

// round 10
// speedup vs baseline: 3.3783x; 1.1012x over previous
#include <cuda_runtime.h>
#include <cuda_bf16.h>
#include <math.h>

// Problem constants
#define BB   32      // batch
#define SS   64      // src len
#define TT   64      // tgt len (63 decode steps)
#define EE   512     // embed dim
#define HH   512     // encoder hidden per dir
#define DDm  1024    // 2*H
#define VV   32000   // vocab

// ---------------------------------------------------------------------------
// Static device scratch
// ---------------------------------------------------------------------------
__device__ __align__(16) float g_embx [BB*SS*EE];
__device__ __align__(16) float g_xgF  [BB*SS*4*HH];
__device__ __align__(16) float g_xgB  [BB*SS*4*HH];
__device__ __align__(16) float g_in1  [BB*SS*DDm];
__device__ __align__(16) float g_enc  [BB*SS*DDm];
__device__ __align__(16) float g_Uenc [BB*SS*DDm];
__device__ __align__(16) float g_hbuf [2*2*2*BB*HH];   // [layer][dir][pp][b*HH+j]
__device__ __align__(16) float g_c    [2*2*BB*HH];
__device__ __align__(16) float g_dh0  [2*BB*DDm];      // ping-pong
__device__ __align__(16) float g_dc0  [BB*DDm];
__device__ __align__(16) float g_dh1  [2*BB*DDm];      // ping-pong
__device__ __align__(16) float g_dc1  [BB*DDm];
__device__ __align__(16) float g_q    [BB*DDm];
__device__ __align__(16) float g_sc   [BB*SS];
__device__ __align__(16) float g_xcat [BB*(EE+DDm)];
__device__ __align__(16) float g_H1   [63*BB*DDm];

// converted activation buffers (u32 = packed bf16 pair, interleaved hi/lo)
__device__ __align__(16) unsigned g_embxc[BB*SS*EE];     // 2048 x 512
__device__ __align__(16) unsigned g_in1c [BB*SS*DDm];    // 2048 x 1024
__device__ __align__(16) unsigned g_encc [BB*SS*DDm];    // 2048 x 1024
__device__ __align__(16) unsigned g_H1c  [2048*DDm];     // padded to 2048 rows

// converted-weight pool
#define OFF_E0F_WIH 0ull
#define OFF_E0B_WIH (OFF_E0F_WIH + 2048ull*512)
#define OFF_E1F_WIH (OFF_E0B_WIH + 2048ull*512)
#define OFF_E1B_WIH (OFF_E1F_WIH + 2048ull*1024)
#define OFF_E0F_WHH (OFF_E1B_WIH + 2048ull*1024)
#define OFF_E0B_WHH (OFF_E0F_WHH + 2048ull*512)
#define OFF_E1F_WHH (OFF_E0B_WHH + 2048ull*512)
#define OFF_E1B_WHH (OFF_E1F_WHH + 2048ull*512)
#define OFF_UA      (OFF_E1B_WHH + 2048ull*512)
#define OFF_WA      (OFF_UA + 1024ull*1024)
#define OFF_D0WIH   (OFF_WA + 1024ull*1024)
#define OFF_D0WHH   (OFF_D0WIH + 4096ull*1536)
#define OFF_D1WIH   (OFF_D0WHH + 4096ull*1024)
#define OFF_D1WHH   (OFF_D1WIH + 4096ull*1024)
#define OFF_FC      (OFF_D1WHH + 4096ull*1024)
#define WCVT_TOTAL  (OFF_FC + 32000ull*1024)
__device__ __align__(16) unsigned g_wcvt[WCVT_TOTAL];

__device__ __forceinline__ float sigf(float v) { return 1.0f/(1.0f + expf(-v)); }

__device__ __forceinline__ float tanha(float x) {
    float r; asm("tanh.approx.f32 %0, %1;" : "=f"(r) : "f"(x)); return r;
}

// fp32 pair -> packed (bf16 hi, bf16 lo)
__device__ __forceinline__ void cvt2(float f0, float f1, unsigned& hi, unsigned& lo) {
    __nv_bfloat16 h0 = __float2bfloat16(f0);
    __nv_bfloat16 h1 = __float2bfloat16(f1);
    __nv_bfloat16 l0 = __float2bfloat16(f0 - __bfloat162float(h0));
    __nv_bfloat16 l1 = __float2bfloat16(f1 - __bfloat162float(h1));
    hi = (unsigned)__bfloat16_as_ushort(h0) | ((unsigned)__bfloat16_as_ushort(h1) << 16);
    lo = (unsigned)__bfloat16_as_ushort(l0) | ((unsigned)__bfloat16_as_ushort(l1) << 16);
}

__device__ __forceinline__ void mma16816(float* c,
    unsigned a0, unsigned a1, unsigned a2, unsigned a3,
    unsigned b0, unsigned b1)
{
    asm volatile(
        "mma.sync.aligned.m16n8k16.row.col.f32.bf16.bf16.f32 "
        "{%0,%1,%2,%3}, {%4,%5,%6,%7}, {%8,%9}, {%0,%1,%2,%3};"
        : "+f"(c[0]), "+f"(c[1]), "+f"(c[2]), "+f"(c[3])
        : "r"(a0), "r"(a1), "r"(a2), "r"(a3), "r"(b0), "r"(b1));
}

// ---------------------------------------------------------------------------
// conversion: fp32 -> interleaved (hiPair, loPair) u32
// ---------------------------------------------------------------------------
__global__ void cvtW(const float* __restrict__ src, unsigned* __restrict__ dst, int np) {
    for (int p = blockIdx.x*blockDim.x + threadIdx.x; p < np; p += gridDim.x*blockDim.x) {
        unsigned h, l;
        cvt2(src[2*p], src[2*p+1], h, l);
        dst[2*p] = h; dst[2*p+1] = l;
    }
}

// ---------------------------------------------------------------------------
// embedding gather with source reversal
// ---------------------------------------------------------------------------
__global__ void embed_rev_kernel(const int* __restrict__ x,
                                 const float* __restrict__ emb_src) {
    int bs = blockIdx.x;
    int b = bs >> 6, s = bs & 63;
    int tok = x[b*SS + (SS-1 - s)];
    const float4* src = (const float4*)(emb_src + (size_t)tok*EE);
    float4* dst = (float4*)(g_embx + (size_t)bs*EE);
    for (int i = threadIdx.x; i < EE/4; i += blockDim.x) dst[i] = src[i];
}

// ---------------------------------------------------------------------------
// bgemm128: split-bf16 mma GEMM, BM=BN=128, BK=32, register prefetch.
// BOTH operands pre-converted (interleaved hi/lo u32). A buffer must be
// padded to a multiple of 128 rows (zeros); epilogue guards M.
// remap=1: row (t*32+b) -> (b*63+t).
// ---------------------------------------------------------------------------
__global__ __launch_bounds__(256) void bgemm128(
    const unsigned* __restrict__ Ahl, const unsigned* __restrict__ Whl,
    const float* __restrict__ bias, float* __restrict__ C,
    int M, int N, int K, int remap)
{
    __shared__ unsigned sAh[128][17], sAl[128][17];
    __shared__ unsigned sWh[128][17], sWl[128][17];

    int tid = threadIdx.x;
    int m0 = blockIdx.x * 128;
    int n0 = blockIdx.y * 128;

    int lane = tid & 31, wid = tid >> 5;
    int wm = (wid & 3) * 32;
    int wn = (wid >> 2) * 64;
    int grp = lane >> 2, q = lane & 3;

    float c[2][8][4];
    #pragma unroll
    for (int mf = 0; mf < 2; mf++)
        #pragma unroll
        for (int nf = 0; nf < 8; nf++)
            #pragma unroll
            for (int i = 0; i < 4; i++) c[mf][nf][i] = 0.f;

    int r  = tid >> 1;
    int ku = (tid & 1) * 16;   // u32 offset within 32-u32 chunk row
    int kp = (tid & 1) * 8;    // pair-column base in smem

    const unsigned* Arow = Ahl + (size_t)(m0 + r)*K + ku;
    const unsigned* Wrow = Whl + (size_t)(n0 + r)*K + ku;

    uint4 pa[4], pw[4];
    #pragma unroll
    for (int i = 0; i < 4; i++) {
        pa[i] = *(const uint4*)(Arow + i*4);
        pw[i] = *(const uint4*)(Wrow + i*4);
    }

    for (int k0 = 0; k0 < K; k0 += 32) {
        __syncthreads();
        #pragma unroll
        for (int i = 0; i < 4; i++) {
            sAh[r][kp+2*i]   = pa[i].x; sAl[r][kp+2*i]   = pa[i].y;
            sAh[r][kp+2*i+1] = pa[i].z; sAl[r][kp+2*i+1] = pa[i].w;
            sWh[r][kp+2*i]   = pw[i].x; sWl[r][kp+2*i]   = pw[i].y;
            sWh[r][kp+2*i+1] = pw[i].z; sWl[r][kp+2*i+1] = pw[i].w;
        }
        __syncthreads();
        if (k0 + 32 < K) {
            #pragma unroll
            for (int i = 0; i < 4; i++) {
                pa[i] = *(const uint4*)(Arow + k0 + 32 + i*4);
                pw[i] = *(const uint4*)(Wrow + k0 + 32 + i*4);
            }
        }

        #pragma unroll
        for (int ks = 0; ks < 2; ks++) {
            int k8 = ks*8;
            unsigned Ah0[2], Ah1[2], Ah2[2], Ah3[2];
            unsigned Al0[2], Al1[2], Al2[2], Al3[2];
            #pragma unroll
            for (int mf = 0; mf < 2; mf++) {
                int mb = wm + mf*16;
                Ah0[mf] = sAh[mb+grp  ][k8+q];   Ah1[mf] = sAh[mb+grp+8][k8+q];
                Ah2[mf] = sAh[mb+grp  ][k8+q+4]; Ah3[mf] = sAh[mb+grp+8][k8+q+4];
                Al0[mf] = sAl[mb+grp  ][k8+q];   Al1[mf] = sAl[mb+grp+8][k8+q];
                Al2[mf] = sAl[mb+grp  ][k8+q+4]; Al3[mf] = sAl[mb+grp+8][k8+q+4];
            }
            #pragma unroll
            for (int nf = 0; nf < 8; nf++) {
                int nb = wn + nf*8;
                unsigned Bh0 = sWh[nb+grp][k8+q], Bh1 = sWh[nb+grp][k8+q+4];
                unsigned Bl0 = sWl[nb+grp][k8+q], Bl1 = sWl[nb+grp][k8+q+4];
                #pragma unroll
                for (int mf = 0; mf < 2; mf++) {
                    mma16816(c[mf][nf], Ah0[mf],Ah1[mf],Ah2[mf],Ah3[mf], Bh0,Bh1);
                    mma16816(c[mf][nf], Ah0[mf],Ah1[mf],Ah2[mf],Ah3[mf], Bl0,Bl1);
                    mma16816(c[mf][nf], Al0[mf],Al1[mf],Al2[mf],Al3[mf], Bh0,Bh1);
                }
            }
        }
    }

    #pragma unroll
    for (int mf = 0; mf < 2; mf++) {
        #pragma unroll
        for (int nf = 0; nf < 8; nf++) {
            int gn = n0 + wn + nf*8 + q*2;
            float b0 = bias[gn], b1 = bias[gn+1];
            int gm0 = m0 + wm + mf*16 + grp;
            int gm1 = gm0 + 8;
            if (gm0 < M) {
                int row = remap ? (gm0 & 31)*63 + (gm0 >> 5) : gm0;
                C[(size_t)row*N + gn]     = c[mf][nf][0] + b0;
                C[(size_t)row*N + gn + 1] = c[mf][nf][1] + b1;
            }
            if (gm1 < M) {
                int row = remap ? (gm1 & 31)*63 + (gm1 >> 5) : gm1;
                C[(size_t)row*N + gn]     = c[mf][nf][2] + b0;
                C[(size_t)row*N + gn + 1] = c[mf][nf][3] + b1;
            }
        }
    }
}

// ---------------------------------------------------------------------------
// BM=32 K-loop (BK=128, register prefetch). A fp32 (cvt in-kernel),
// W pre-converted. Warp layout: mh = wid&1 (m16), wn = wid>>1 (n8).
// ---------------------------------------------------------------------------
__device__ __forceinline__ void kloop128(
    const float* __restrict__ Arow, const unsigned* __restrict__ Wrow, int K,
    unsigned (*sAh)[65], unsigned (*sAl)[65],
    unsigned (*sWh)[65], unsigned (*sWl)[65],
    float* cacc, int r, int c8, int mh, int wn, int grp, int qq)
{
    float4 fa[4]; uint4 uw[4];
    #pragma unroll
    for (int i = 0; i < 4; i++) {
        fa[i] = *(const float4*)(Arow + (c8 + i*8)*4);
        uw[i] = *(const uint4*)(Wrow + (c8 + i*8)*4);
    }
    for (int k0 = 0; k0 < K; k0 += 128) {
        __syncthreads();
        #pragma unroll
        for (int i = 0; i < 4; i++) {
            int col = (c8 + i*8)*2;
            unsigned h0,l0,h1,l1;
            cvt2(fa[i].x, fa[i].y, h0, l0);
            cvt2(fa[i].z, fa[i].w, h1, l1);
            sAh[r][col]=h0; sAl[r][col]=l0; sAh[r][col+1]=h1; sAl[r][col+1]=l1;
            sWh[r][col]=uw[i].x; sWl[r][col]=uw[i].y;
            sWh[r][col+1]=uw[i].z; sWl[r][col+1]=uw[i].w;
        }
        __syncthreads();
        if (k0 + 128 < K) {
            #pragma unroll
            for (int i = 0; i < 4; i++) {
                fa[i] = *(const float4*)(Arow + k0 + 128 + (c8 + i*8)*4);
                uw[i] = *(const uint4*)(Wrow + k0 + 128 + (c8 + i*8)*4);
            }
        }
        #pragma unroll
        for (int ks = 0; ks < 8; ks++) {
            int k8 = ks*8;
            int mb = mh*16;
            unsigned Ah0 = sAh[mb+grp  ][k8+qq],  Ah1 = sAh[mb+grp+8][k8+qq];
            unsigned Ah2 = sAh[mb+grp  ][k8+qq+4],Ah3 = sAh[mb+grp+8][k8+qq+4];
            unsigned Al0 = sAl[mb+grp  ][k8+qq],  Al1 = sAl[mb+grp+8][k8+qq];
            unsigned Al2 = sAl[mb+grp  ][k8+qq+4],Al3 = sAl[mb+grp+8][k8+qq+4];
            unsigned Bh0 = sWh[wn*8+grp][k8+qq],  Bh1 = sWh[wn*8+grp][k8+qq+4];
            unsigned Bl0 = sWl[wn*8+grp][k8+qq],  Bl1 = sWl[wn*8+grp][k8+qq+4];
            mma16816(cacc, Ah0,Ah1,Ah2,Ah3, Bh0,Bh1);
            mma16816(cacc, Ah0,Ah1,Ah2,Ah3, Bl0,Bl1);
            mma16816(cacc, Al0,Al1,Al2,Al3, Bh0,Bh1);
        }
    }
}

// ---------------------------------------------------------------------------
// cell32: fused gates-GEMM + LSTM cell (validated in R8)
// ---------------------------------------------------------------------------
struct CArg {
    const float* A1; const unsigned* W1; int K1;
    const float* A2; const unsigned* W2; int K2;
    int NH;
    const float* gadd; int gaddB;
    float* cst;
    float* hout;
    float* out2; int out2B;
};

__global__ __launch_bounds__(256) void cell32(CArg pa, CArg pb) {
    const CArg p = blockIdx.y ? pb : pa;
    __shared__ unsigned sAh[32][65], sAl[32][65], sWh[32][65], sWl[32][65];
    int tid = threadIdx.x;
    int r = tid >> 3, c8 = tid & 7;
    int lane = tid & 31, wid = tid >> 5;
    int mh = wid & 1, wn = wid >> 1, grp = lane >> 2, qq = lane & 3;
    int j0 = blockIdx.x * 8;
    size_t wrow = (size_t)(r >> 3)*p.NH + j0 + (r & 7);

    float cacc[4] = {0.f, 0.f, 0.f, 0.f};
    kloop128(p.A1 + (size_t)r*p.K1, p.W1 + wrow*p.K1, p.K1,
             sAh, sAl, sWh, sWl, cacc, r, c8, mh, wn, grp, qq);
    if (p.K2)
        kloop128(p.A2 + (size_t)r*p.K2, p.W2 + wrow*p.K2, p.K2,
                 sAh, sAl, sWh, sWl, cacc, r, c8, mh, wn, grp, qq);

    __syncthreads();
    float (*gsm)[33] = (float(*)[33])&sAh[0][0];
    int n = wn*8 + 2*qq;
    int b0 = mh*16 + grp;
    gsm[b0][n]   = cacc[0]; gsm[b0][n+1]   = cacc[1];
    gsm[b0+8][n] = cacc[2]; gsm[b0+8][n+1] = cacc[3];
    __syncthreads();

    int b = tid & 31, jj = tid >> 5, j = j0 + jj;
    size_t gb = (size_t)b * p.gaddB;
    float gi = gsm[b][jj]      + p.gadd[gb + 0*p.NH + j];
    float gf = gsm[b][8+jj]    + p.gadd[gb + 1*p.NH + j];
    float gg = gsm[b][16+jj]   + p.gadd[gb + 2*p.NH + j];
    float go = gsm[b][24+jj]   + p.gadd[gb + 3*p.NH + j];
    int ci = b*p.NH + j;
    float cc = sigf(gf)*p.cst[ci] + sigf(gi)*tanhf(gg);
    p.cst[ci] = cc;
    float hh = sigf(go)*tanhf(cc);
    p.hout[ci] = hh;
    if (p.out2) p.out2[(size_t)b*p.out2B + j] = hh;
}

// ---------------------------------------------------------------------------
// qgemm32: BM=32 GEMM (q = h1 @ Wa^T + bias)
// ---------------------------------------------------------------------------
__global__ __launch_bounds__(256) void qgemm32(
    const float* __restrict__ A, const unsigned* __restrict__ W,
    const float* __restrict__ bias, float* __restrict__ C, int K, int N)
{
    __shared__ unsigned sAh[32][65], sAl[32][65], sWh[32][65], sWl[32][65];
    int tid = threadIdx.x;
    int r = tid >> 3, c8 = tid & 7;
    int lane = tid & 31, wid = tid >> 5;
    int mh = wid & 1, wn = wid >> 1, grp = lane >> 2, qq = lane & 3;
    int n0 = blockIdx.x * 32;

    float cacc[4] = {0.f, 0.f, 0.f, 0.f};
    kloop128(A + (size_t)r*K, W + (size_t)(n0 + r)*K, K,
             sAh, sAl, sWh, sWl, cacc, r, c8, mh, wn, grp, qq);

    int gn = n0 + wn*8 + 2*qq;
    int b0 = mh*16 + grp;
    C[(size_t)b0*N + gn]       = cacc[0] + bias[gn];
    C[(size_t)b0*N + gn + 1]   = cacc[1] + bias[gn+1];
    C[(size_t)(b0+8)*N + gn]   = cacc[2] + bias[gn];
    C[(size_t)(b0+8)*N + gn+1] = cacc[3] + bias[gn+1];
}

// ---------------------------------------------------------------------------
// decoder initial state
// ---------------------------------------------------------------------------
__global__ void dec_init() {
    int idx = blockIdx.x*256 + threadIdx.x;
    if (idx >= BB*HH) return;
    int b = idx >> 9, j = idx & 511;
    const int NP = BB*HH;
    float h0f = g_hbuf[(size_t)((0*2+0)*2+0)*NP + idx];
    float h0b = g_hbuf[(size_t)((0*2+1)*2+0)*NP + idx];
    float h1f = g_hbuf[(size_t)((1*2+0)*2+0)*NP + idx];
    float h1b = g_hbuf[(size_t)((1*2+1)*2+0)*NP + idx];
    float c0f = g_c[(size_t)(0*2+0)*NP + idx];
    float c0b = g_c[(size_t)(0*2+1)*NP + idx];
    float c1f = g_c[(size_t)(1*2+0)*NP + idx];
    float c1b = g_c[(size_t)(1*2+1)*NP + idx];
    g_dh0[b*DDm + j]      = h0f;  g_dh0[b*DDm + HH + j] = h0b;
    g_dc0[b*DDm + j]      = c0f;  g_dc0[b*DDm + HH + j] = c0b;
    g_dh1[b*DDm + j]      = h1f;  g_dh1[b*DDm + HH + j] = h1b;
    g_dc1[b*DDm + j]      = c1f;  g_dc1[b*DDm + HH + j] = c1b;
}

// ---------------------------------------------------------------------------
// attention scores: warp per (b,s). tanh.approx (scores path only).
// ---------------------------------------------------------------------------
__global__ __launch_bounds__(256) void att_scores2(const float* __restrict__ va) {
    int lane = threadIdx.x & 31, w = threadIdx.x >> 5;
    int task = blockIdx.x*8 + w;
    int b = task >> 6;
    const float* u  = g_Uenc + (size_t)task*DDm;
    const float* qq = g_q + (size_t)b*DDm;
    float p = 0.f;
    #pragma unroll 8
    for (int e = lane; e < DDm; e += 32)
        p += va[e]*tanha(qq[e] + u[e]);
    #pragma unroll
    for (int off = 16; off; off >>= 1)
        p += __shfl_xor_sync(0xffffffffu, p, off);
    if (lane == 0) g_sc[task] = p;
}

// ---------------------------------------------------------------------------
// softmax + context + target-embedding gather. grid 128 = (b, quarter).
// ---------------------------------------------------------------------------
__global__ __launch_bounds__(256) void softmax_ctx2(
    const int* __restrict__ y, const float* __restrict__ emb_tgt, int t)
{
    __shared__ float w[SS];
    int b = blockIdx.x >> 2, quarter = blockIdx.x & 3;
    int tid = threadIdx.x;
    if (tid < SS) w[tid] = g_sc[b*SS + tid];
    __syncthreads();
    if (tid == 0) {
        float mx = w[0];
        for (int s = 1; s < SS; s++) mx = fmaxf(mx, w[s]);
        float sm = 0.f;
        for (int s = 0; s < SS; s++) { w[s] = expf(w[s]-mx); sm += w[s]; }
        float inv = 1.0f/sm;
        for (int s = 0; s < SS; s++) w[s] *= inv;
    }
    __syncthreads();
    int d = quarter*256 + tid;
    {
        float acc = 0.f;
        const float* e = g_enc + (size_t)(b*SS)*DDm + d;
        #pragma unroll 8
        for (int s = 0; s < SS; s++) acc += w[s]*e[(size_t)s*DDm];
        g_xcat[(size_t)b*(EE+DDm) + EE + d] = acc;
    }
    if (quarter < 2) {
        int ei = quarter*256 + tid;
        int tok = y[b*TT + t];
        g_xcat[(size_t)b*(EE+DDm) + ei] = emb_tgt[(size_t)tok*EE + ei];
    }
}

// ---------------------------------------------------------------------------
// host driver
// ---------------------------------------------------------------------------
static float* symf(const void* s) {
    void* p = nullptr;
    cudaGetSymbolAddress(&p, s);
    return (float*)p;
}

extern "C" void kernel_launch(void* const* d_in, const int* in_sizes, int n_in,
                              void* d_out, int out_size) {
    const int*   x        = (const int*)  d_in[0];
    const int*   y        = (const int*)  d_in[1];
    const float* emb_src  = (const float*)d_in[2];
    const float* emb_tgt  = (const float*)d_in[3];
    const float* e0f_wih  = (const float*)d_in[4];
    const float* e0f_whh  = (const float*)d_in[5];
    const float* e0f_b    = (const float*)d_in[6];
    const float* e0b_wih  = (const float*)d_in[7];
    const float* e0b_whh  = (const float*)d_in[8];
    const float* e0b_b    = (const float*)d_in[9];
    const float* e1f_wih  = (const float*)d_in[10];
    const float* e1f_whh  = (const float*)d_in[11];
    const float* e1f_b    = (const float*)d_in[12];
    const float* e1b_wih  = (const float*)d_in[13];
    const float* e1b_whh  = (const float*)d_in[14];
    const float* e1b_b    = (const float*)d_in[15];
    const float* Wa_w     = (const float*)d_in[16];
    const float* Wa_b     = (const float*)d_in[17];
    const float* Ua_w     = (const float*)d_in[18];
    const float* Ua_b     = (const float*)d_in[19];
    const float* va_w     = (const float*)d_in[20];
    const float* d0_wih   = (const float*)d_in[21];
    const float* d0_whh   = (const float*)d_in[22];
    const float* d0_b     = (const float*)d_in[23];
    const float* d1_wih   = (const float*)d_in[24];
    const float* d1_whh   = (const float*)d_in[25];
    const float* d1_b     = (const float*)d_in[26];
    const float* fc_w     = (const float*)d_in[27];
    const float* fc_b     = (const float*)d_in[28];
    float* out = (float*)d_out;

    float* p_embx = symf(g_embx);
    float* p_xgF  = symf(g_xgF);
    float* p_xgB  = symf(g_xgB);
    float* p_in1  = symf(g_in1);
    float* p_enc  = symf(g_enc);
    float* p_Uenc = symf(g_Uenc);
    float* p_hbuf = symf(g_hbuf);
    float* p_c    = symf(g_c);
    float* p_dh0  = symf(g_dh0);
    float* p_dc0  = symf(g_dc0);
    float* p_dh1  = symf(g_dh1);
    float* p_dc1  = symf(g_dc1);
    float* p_q    = symf(g_q);
    float* p_xcat = symf(g_xcat);
    float* p_H1   = symf(g_H1);
    unsigned* p_w     = (unsigned*)symf(g_wcvt);
    unsigned* p_embxc = (unsigned*)symf(g_embxc);
    unsigned* p_in1c  = (unsigned*)symf(g_in1c);
    unsigned* p_encc  = (unsigned*)symf(g_encc);
    unsigned* p_H1c   = (unsigned*)symf(g_H1c);

    const int M = BB*SS;   // 2048

    // 0) convert all weights to split-bf16 pairs
    {
        struct { const float* s; size_t off; size_t n; } cv[15] = {
            { e0f_wih, OFF_E0F_WIH, 2048ull*512  },
            { e0b_wih, OFF_E0B_WIH, 2048ull*512  },
            { e1f_wih, OFF_E1F_WIH, 2048ull*1024 },
            { e1b_wih, OFF_E1B_WIH, 2048ull*1024 },
            { e0f_whh, OFF_E0F_WHH, 2048ull*512  },
            { e0b_whh, OFF_E0B_WHH, 2048ull*512  },
            { e1f_whh, OFF_E1F_WHH, 2048ull*512  },
            { e1b_whh, OFF_E1B_WHH, 2048ull*512  },
            { Ua_w,    OFF_UA,      1024ull*1024 },
            { Wa_w,    OFF_WA,      1024ull*1024 },
            { d0_wih,  OFF_D0WIH,   4096ull*1536 },
            { d0_whh,  OFF_D0WHH,   4096ull*1024 },
            { d1_wih,  OFF_D1WIH,   4096ull*1024 },
            { d1_whh,  OFF_D1WHH,   4096ull*1024 },
            { fc_w,    OFF_FC,      32000ull*1024 },
        };
        for (int i = 0; i < 15; i++)
            cvtW<<<256, 256>>>(cv[i].s, p_w + cv[i].off, (int)(cv[i].n/2));
    }

    // 1) embedding + reverse, then convert
    embed_rev_kernel<<<BB*SS, 128>>>(x, emb_src);
    cvtW<<<256, 256>>>(p_embx, p_embxc, BB*SS*EE/2);

    // 2) layer-0 input GEMMs
    {
        dim3 grid(M/128, (4*HH)/128);
        bgemm128<<<grid, 256>>>(p_embxc, p_w + OFF_E0F_WIH, e0f_b, p_xgF, M, 4*HH, EE, 0);
        bgemm128<<<grid, 256>>>(p_embxc, p_w + OFF_E0B_WIH, e0b_b, p_xgB, M, 4*HH, EE, 0);
    }

    cudaMemsetAsync(p_hbuf, 0, sizeof(float)*2*2*2*BB*HH);
    cudaMemsetAsync(p_c,    0, sizeof(float)*2*2*BB*HH);

    // 3+5) encoder recurrences (fused gates+cell, both dirs per launch)
    const size_t whhOff[2][2] = { {OFF_E0F_WHH, OFF_E0B_WHH}, {OFF_E1F_WHH, OFF_E1B_WHH} };
    for (int layer = 0; layer < 2; layer++) {
        if (layer == 1) {
            cvtW<<<256, 256>>>(p_in1, p_in1c, BB*SS*DDm/2);
            dim3 grid(M/128, (4*HH)/128);
            bgemm128<<<grid, 256>>>(p_in1c, p_w + OFF_E1F_WIH, e1f_b, p_xgF, M, 4*HH, DDm, 0);
            bgemm128<<<grid, 256>>>(p_in1c, p_w + OFF_E1B_WIH, e1b_b, p_xgB, M, 4*HH, DDm, 0);
        }
        float* outb = layer ? p_enc : p_in1;
        for (int s = 0; s < SS; s++) {
            int pp = s & 1;
            CArg a{}, bg{};
            a.A1 = p_hbuf + (size_t)((layer*2+0)*2 + pp)*(BB*HH);
            a.W1 = p_w + whhOff[layer][0]; a.K1 = HH;
            a.A2 = nullptr; a.W2 = nullptr; a.K2 = 0;
            a.NH = HH;
            a.gadd = p_xgF + (size_t)s*4*HH;  a.gaddB = SS*4*HH;
            a.cst  = p_c + (size_t)(layer*2+0)*(BB*HH);
            a.hout = p_hbuf + (size_t)((layer*2+0)*2 + (pp^1))*(BB*HH);
            a.out2 = outb + (size_t)s*DDm;    a.out2B = SS*DDm;
            int s1 = 63 - s;
            bg.A1 = p_hbuf + (size_t)((layer*2+1)*2 + pp)*(BB*HH);
            bg.W1 = p_w + whhOff[layer][1]; bg.K1 = HH;
            bg.A2 = nullptr; bg.W2 = nullptr; bg.K2 = 0;
            bg.NH = HH;
            bg.gadd = p_xgB + (size_t)s1*4*HH; bg.gaddB = SS*4*HH;
            bg.cst  = p_c + (size_t)(layer*2+1)*(BB*HH);
            bg.hout = p_hbuf + (size_t)((layer*2+1)*2 + (pp^1))*(BB*HH);
            bg.out2 = outb + (size_t)s1*DDm + HH; bg.out2B = SS*DDm;
            cell32<<<dim3(HH/8, 2), 256>>>(a, bg);
        }
    }

    // 6) Uenc = enc @ Ua^T + Ua_b
    cvtW<<<256, 256>>>(p_enc, p_encc, BB*SS*DDm/2);
    {
        dim3 grid(M/128, DDm/128);
        bgemm128<<<grid, 256>>>(p_encc, p_w + OFF_UA, Ua_b, p_Uenc, M, DDm, DDm, 0);
    }

    // 7) decoder initial state
    dec_init<<<(BB*HH + 255)/256, 256>>>();

    // 8) decoder steps (5 launches per step)
    for (int t = 0; t < TT-1; t++) {
        int pp = t & 1;
        float* h0r = p_dh0 + (size_t)pp*(BB*DDm);
        float* h0w = p_dh0 + (size_t)(pp^1)*(BB*DDm);
        float* h1r = p_dh1 + (size_t)pp*(BB*DDm);
        float* h1w = p_dh1 + (size_t)(pp^1)*(BB*DDm);

        qgemm32<<<DDm/32, 256>>>(h1r, p_w + OFF_WA, Wa_b, p_q, DDm, DDm);
        att_scores2<<<256, 256>>>(va_w);
        softmax_ctx2<<<128, 256>>>(y, emb_tgt, t);

        CArg c0{};
        c0.A1 = p_xcat; c0.W1 = p_w + OFF_D0WIH; c0.K1 = EE+DDm;
        c0.A2 = h0r;    c0.W2 = p_w + OFF_D0WHH; c0.K2 = DDm;
        c0.NH = DDm; c0.gadd = d0_b; c0.gaddB = 0;
        c0.cst = p_dc0; c0.hout = h0w; c0.out2 = nullptr; c0.out2B = 0;
        cell32<<<dim3(DDm/8, 1), 256>>>(c0, c0);

        CArg c1{};
        c1.A1 = h0w; c1.W1 = p_w + OFF_D1WIH; c1.K1 = DDm;
        c1.A2 = h1r; c1.W2 = p_w + OFF_D1WHH; c1.K2 = DDm;
        c1.NH = DDm; c1.gadd = d1_b; c1.gaddB = 0;
        c1.cst = p_dc1; c1.hout = h1w;
        c1.out2 = p_H1 + (size_t)t*BB*DDm; c1.out2B = DDm;
        cell32<<<dim3(DDm/8, 1), 256>>>(c1, c1);
    }

    // 9) deferred logits GEMM: convert H1 (pad rows 2016..2047 with zeros)
    cudaMemsetAsync(p_H1c + 2016ull*DDm, 0, 32ull*DDm*sizeof(unsigned));
    cvtW<<<256, 256>>>(p_H1, p_H1c, 63*BB*DDm/2);
    {
        int Mf = 63*BB;   // 2016
        dim3 grid(2048/128, VV/128);
        bgemm128<<<grid, 256>>>(p_H1c, p_w + OFF_FC, fc_b, out, Mf, VV, DDm, 1);
    }
}

// round 14
// speedup vs baseline: 3.4582x; 1.0236x over previous
#include <cuda_runtime.h>
#include <cuda_bf16.h>
#include <math.h>

// Problem constants
#define BB   32      // batch
#define SS   64      // src len
#define TT   64      // tgt len (63 decode steps)
#define EE   512     // embed dim
#define HH   512     // encoder hidden per dir
#define DDm  1024    // 2*H
#define VV   32000   // vocab

// ---------------------------------------------------------------------------
// Static device scratch
// ---------------------------------------------------------------------------
__device__ __align__(16) float g_embx [BB*SS*EE];
__device__ __align__(16) float g_xgF  [BB*SS*4*HH];
__device__ __align__(16) float g_xgB  [BB*SS*4*HH];
__device__ __align__(16) float g_in1  [BB*SS*DDm];
__device__ __align__(16) float g_enc  [BB*SS*DDm];
__device__ __align__(16) float g_Uenc [BB*SS*DDm];
__device__ __align__(16) float g_hbuf [2*2*2*BB*HH];   // [layer][dir][pp][b*HH+j]
__device__ __align__(16) float g_c    [2*2*BB*HH];
__device__ __align__(16) float g_dh0  [2*BB*DDm];      // ping-pong
__device__ __align__(16) float g_dc0  [BB*DDm];
__device__ __align__(16) float g_dh1  [2*BB*DDm];      // ping-pong
__device__ __align__(16) float g_dc1  [BB*DDm];
__device__ __align__(16) float g_q    [BB*DDm];
__device__ __align__(16) float g_sc   [BB*SS];
__device__ __align__(16) float g_xcat [BB*(EE+DDm)];
__device__ __align__(16) float g_H1   [63*BB*DDm];

// converted activation buffers (u32 = packed bf16 pair, interleaved hi/lo)
__device__ __align__(16) unsigned g_embxc[BB*SS*EE];
__device__ __align__(16) unsigned g_in1c [BB*SS*DDm];
__device__ __align__(16) unsigned g_encc [BB*SS*DDm];
__device__ __align__(16) unsigned g_H1c  [2048*DDm];     // padded to 2048 rows

// converted-weight pool
#define OFF_E0F_WIH 0ull
#define OFF_E0B_WIH (OFF_E0F_WIH + 2048ull*512)
#define OFF_E1F_WIH (OFF_E0B_WIH + 2048ull*512)
#define OFF_E1B_WIH (OFF_E1F_WIH + 2048ull*1024)
#define OFF_E0F_WHH (OFF_E1B_WIH + 2048ull*1024)
#define OFF_E0B_WHH (OFF_E0F_WHH + 2048ull*512)
#define OFF_E1F_WHH (OFF_E0B_WHH + 2048ull*512)
#define OFF_E1B_WHH (OFF_E1F_WHH + 2048ull*512)
#define OFF_UA      (OFF_E1B_WHH + 2048ull*512)
#define OFF_WA      (OFF_UA + 1024ull*1024)
#define OFF_D0WIH   (OFF_WA + 1024ull*1024)
#define OFF_D0WHH   (OFF_D0WIH + 4096ull*1536)
#define OFF_D1WIH   (OFF_D0WHH + 4096ull*1024)
#define OFF_D1WHH   (OFF_D1WIH + 4096ull*1024)
#define OFF_FC      (OFF_D1WHH + 4096ull*1024)
#define WCVT_TOTAL  (OFF_FC + 32000ull*1024)
__device__ __align__(16) unsigned g_wcvt[WCVT_TOTAL];

__device__ __forceinline__ float sigf(float v) { return 1.0f/(1.0f + expf(-v)); }

__device__ __forceinline__ float tanha(float x) {
    float r; asm("tanh.approx.f32 %0, %1;" : "=f"(r) : "f"(x)); return r;
}

// fp32 pair -> packed (bf16 hi, bf16 lo)
__device__ __forceinline__ void cvt2(float f0, float f1, unsigned& hi, unsigned& lo) {
    __nv_bfloat16 h0 = __float2bfloat16(f0);
    __nv_bfloat16 h1 = __float2bfloat16(f1);
    __nv_bfloat16 l0 = __float2bfloat16(f0 - __bfloat162float(h0));
    __nv_bfloat16 l1 = __float2bfloat16(f1 - __bfloat162float(h1));
    hi = (unsigned)__bfloat16_as_ushort(h0) | ((unsigned)__bfloat16_as_ushort(h1) << 16);
    lo = (unsigned)__bfloat16_as_ushort(l0) | ((unsigned)__bfloat16_as_ushort(l1) << 16);
}

__device__ __forceinline__ void mma16816(float* c,
    unsigned a0, unsigned a1, unsigned a2, unsigned a3,
    unsigned b0, unsigned b1)
{
    asm volatile(
        "mma.sync.aligned.m16n8k16.row.col.f32.bf16.bf16.f32 "
        "{%0,%1,%2,%3}, {%4,%5,%6,%7}, {%8,%9}, {%0,%1,%2,%3};"
        : "+f"(c[0]), "+f"(c[1]), "+f"(c[2]), "+f"(c[3])
        : "r"(a0), "r"(a1), "r"(a2), "r"(a3), "r"(b0), "r"(b1));
}

// ---------------------------------------------------------------------------
// vectorized conversion: float4 -> uint4 (2x cvt2 pairs)
// ---------------------------------------------------------------------------
__global__ void cvtW4(const float4* __restrict__ src, uint4* __restrict__ dst, int n4) {
    for (int i = blockIdx.x*blockDim.x + threadIdx.x; i < n4; i += gridDim.x*blockDim.x) {
        float4 v = src[i];
        unsigned h0, l0, h1, l1;
        cvt2(v.x, v.y, h0, l0);
        cvt2(v.z, v.w, h1, l1);
        dst[i] = make_uint4(h0, l0, h1, l1);
    }
}

// ---------------------------------------------------------------------------
// embedding gather with source reversal
// ---------------------------------------------------------------------------
__global__ void embed_rev_kernel(const int* __restrict__ x,
                                 const float* __restrict__ emb_src) {
    int bs = blockIdx.x;
    int b = bs >> 6, s = bs & 63;
    int tok = x[b*SS + (SS-1 - s)];
    const float4* src = (const float4*)(emb_src + (size_t)tok*EE);
    float4* dst = (float4*)(g_embx + (size_t)bs*EE);
    for (int i = threadIdx.x; i < EE/4; i += blockDim.x) dst[i] = src[i];
}

// ---------------------------------------------------------------------------
// bgemm128: split-bf16 mma GEMM, BM=BN=128, BK=32, register prefetch.
// Both operands pre-converted. A padded to multiple of 128 rows.
// remap=1: row (t*32+b) -> (b*63+t).
// ---------------------------------------------------------------------------
__global__ __launch_bounds__(256) void bgemm128(
    const unsigned* __restrict__ Ahl, const unsigned* __restrict__ Whl,
    const float* __restrict__ bias, float* __restrict__ C,
    int M, int N, int K, int remap)
{
    __shared__ unsigned sAh[128][17], sAl[128][17];
    __shared__ unsigned sWh[128][17], sWl[128][17];

    int tid = threadIdx.x;
    int m0 = blockIdx.x * 128;
    int n0 = blockIdx.y * 128;

    int lane = tid & 31, wid = tid >> 5;
    int wm = (wid & 3) * 32;
    int wn = (wid >> 2) * 64;
    int grp = lane >> 2, q = lane & 3;

    float c[2][8][4];
    #pragma unroll
    for (int mf = 0; mf < 2; mf++)
        #pragma unroll
        for (int nf = 0; nf < 8; nf++)
            #pragma unroll
            for (int i = 0; i < 4; i++) c[mf][nf][i] = 0.f;

    int r  = tid >> 1;
    int ku = (tid & 1) * 16;
    int kp = (tid & 1) * 8;

    const unsigned* Arow = Ahl + (size_t)(m0 + r)*K + ku;
    const unsigned* Wrow = Whl + (size_t)(n0 + r)*K + ku;

    uint4 pa[4], pw[4];
    #pragma unroll
    for (int i = 0; i < 4; i++) {
        pa[i] = *(const uint4*)(Arow + i*4);
        pw[i] = *(const uint4*)(Wrow + i*4);
    }

    for (int k0 = 0; k0 < K; k0 += 32) {
        __syncthreads();
        #pragma unroll
        for (int i = 0; i < 4; i++) {
            sAh[r][kp+2*i]   = pa[i].x; sAl[r][kp+2*i]   = pa[i].y;
            sAh[r][kp+2*i+1] = pa[i].z; sAl[r][kp+2*i+1] = pa[i].w;
            sWh[r][kp+2*i]   = pw[i].x; sWl[r][kp+2*i]   = pw[i].y;
            sWh[r][kp+2*i+1] = pw[i].z; sWl[r][kp+2*i+1] = pw[i].w;
        }
        __syncthreads();
        if (k0 + 32 < K) {
            #pragma unroll
            for (int i = 0; i < 4; i++) {
                pa[i] = *(const uint4*)(Arow + k0 + 32 + i*4);
                pw[i] = *(const uint4*)(Wrow + k0 + 32 + i*4);
            }
        }

        #pragma unroll
        for (int ks = 0; ks < 2; ks++) {
            int k8 = ks*8;
            unsigned Ah0[2], Ah1[2], Ah2[2], Ah3[2];
            unsigned Al0[2], Al1[2], Al2[2], Al3[2];
            #pragma unroll
            for (int mf = 0; mf < 2; mf++) {
                int mb = wm + mf*16;
                Ah0[mf] = sAh[mb+grp  ][k8+q];   Ah1[mf] = sAh[mb+grp+8][k8+q];
                Ah2[mf] = sAh[mb+grp  ][k8+q+4]; Ah3[mf] = sAh[mb+grp+8][k8+q+4];
                Al0[mf] = sAl[mb+grp  ][k8+q];   Al1[mf] = sAl[mb+grp+8][k8+q];
                Al2[mf] = sAl[mb+grp  ][k8+q+4]; Al3[mf] = sAl[mb+grp+8][k8+q+4];
            }
            #pragma unroll
            for (int nf = 0; nf < 8; nf++) {
                int nb = wn + nf*8;
                unsigned Bh0 = sWh[nb+grp][k8+q], Bh1 = sWh[nb+grp][k8+q+4];
                unsigned Bl0 = sWl[nb+grp][k8+q], Bl1 = sWl[nb+grp][k8+q+4];
                #pragma unroll
                for (int mf = 0; mf < 2; mf++) {
                    mma16816(c[mf][nf], Ah0[mf],Ah1[mf],Ah2[mf],Ah3[mf], Bh0,Bh1);
                    mma16816(c[mf][nf], Ah0[mf],Ah1[mf],Ah2[mf],Ah3[mf], Bl0,Bl1);
                    mma16816(c[mf][nf], Al0[mf],Al1[mf],Al2[mf],Al3[mf], Bh0,Bh1);
                }
            }
        }
    }

    #pragma unroll
    for (int mf = 0; mf < 2; mf++) {
        #pragma unroll
        for (int nf = 0; nf < 8; nf++) {
            int gn = n0 + wn + nf*8 + q*2;
            float b0 = bias[gn], b1 = bias[gn+1];
            int gm0 = m0 + wm + mf*16 + grp;
            int gm1 = gm0 + 8;
            if (gm0 < M) {
                int row = remap ? (gm0 & 31)*63 + (gm0 >> 5) : gm0;
                C[(size_t)row*N + gn]     = c[mf][nf][0] + b0;
                C[(size_t)row*N + gn + 1] = c[mf][nf][1] + b1;
            }
            if (gm1 < M) {
                int row = remap ? (gm1 & 31)*63 + (gm1 >> 5) : gm1;
                C[(size_t)row*N + gn]     = c[mf][nf][2] + b0;
                C[(size_t)row*N + gn + 1] = c[mf][nf][3] + b1;
            }
        }
    }
}

// ---------------------------------------------------------------------------
// BM=32 K-loop, BK=128, DOUBLE-BUFFERED smem + register prefetch.
// Layout in dynamic smem: stage s at sm + s*4*2080; within a stage:
// sAh @0, sAl @2080, sWh @4160, sWl @6240 (row stride 65 u32).
// One __syncthreads per chunk; next-chunk global loads overlap mma.
// ---------------------------------------------------------------------------
#define STG (4*2080)
__device__ __forceinline__ void kloop2(
    const float* __restrict__ Arow, const unsigned* __restrict__ Wrow, int K,
    unsigned* __restrict__ sm,
    float* cacc, int r, int c8, int mh, int wn, int grp, int qq, int& buf)
{
    float4 fa[4]; uint4 uw[4];
    #pragma unroll
    for (int i = 0; i < 4; i++) {
        fa[i] = *(const float4*)(Arow + (c8 + i*8)*4);
        uw[i] = *(const uint4*)(Wrow + (c8 + i*8)*4);
    }
    for (int k0 = 0; k0 < K; k0 += 128) {
        unsigned* sAh = sm + buf*STG;
        unsigned* sAl = sAh + 2080;
        unsigned* sWh = sAh + 4160;
        unsigned* sWl = sAh + 6240;
        #pragma unroll
        for (int i = 0; i < 4; i++) {
            int col = (c8 + i*8)*2;
            unsigned h0,l0,h1,l1;
            cvt2(fa[i].x, fa[i].y, h0, l0);
            cvt2(fa[i].z, fa[i].w, h1, l1);
            sAh[r*65+col]=h0; sAl[r*65+col]=l0; sAh[r*65+col+1]=h1; sAl[r*65+col+1]=l1;
            sWh[r*65+col]=uw[i].x; sWl[r*65+col]=uw[i].y;
            sWh[r*65+col+1]=uw[i].z; sWl[r*65+col+1]=uw[i].w;
        }
        __syncthreads();
        if (k0 + 128 < K) {
            #pragma unroll
            for (int i = 0; i < 4; i++) {
                fa[i] = *(const float4*)(Arow + k0 + 128 + (c8 + i*8)*4);
                uw[i] = *(const uint4*)(Wrow + k0 + 128 + (c8 + i*8)*4);
            }
        }
        #pragma unroll
        for (int ks = 0; ks < 8; ks++) {
            int k8 = ks*8;
            int mb = mh*16;
            unsigned Ah0 = sAh[(mb+grp)*65+k8+qq],   Ah1 = sAh[(mb+grp+8)*65+k8+qq];
            unsigned Ah2 = sAh[(mb+grp)*65+k8+qq+4], Ah3 = sAh[(mb+grp+8)*65+k8+qq+4];
            unsigned Al0 = sAl[(mb+grp)*65+k8+qq],   Al1 = sAl[(mb+grp+8)*65+k8+qq];
            unsigned Al2 = sAl[(mb+grp)*65+k8+qq+4], Al3 = sAl[(mb+grp+8)*65+k8+qq+4];
            unsigned Bh0 = sWh[(wn*8+grp)*65+k8+qq], Bh1 = sWh[(wn*8+grp)*65+k8+qq+4];
            unsigned Bl0 = sWl[(wn*8+grp)*65+k8+qq], Bl1 = sWl[(wn*8+grp)*65+k8+qq+4];
            mma16816(cacc, Ah0,Ah1,Ah2,Ah3, Bh0,Bh1);
            mma16816(cacc, Ah0,Ah1,Ah2,Ah3, Bl0,Bl1);
            mma16816(cacc, Al0,Al1,Al2,Al3, Bh0,Bh1);
        }
        buf ^= 1;
    }
}

#define CELL_SMEM (2*STG*4)   // bytes: 2 stages * 4 arrays * 2080 u32

// ---------------------------------------------------------------------------
// cell32: fused gates-GEMM + LSTM cell (double-buffered kloop)
// ---------------------------------------------------------------------------
struct CArg {
    const float* A1; const unsigned* W1; int K1;
    const float* A2; const unsigned* W2; int K2;
    int NH;
    const float* gadd; int gaddB;
    float* cst;
    float* hout;
    float* out2; int out2B;
};

__global__ __launch_bounds__(256) void cell32(CArg pa, CArg pb) {
    const CArg p = blockIdx.y ? pb : pa;
    extern __shared__ unsigned smx[];
    int tid = threadIdx.x;
    int r = tid >> 3, c8 = tid & 7;
    int lane = tid & 31, wid = tid >> 5;
    int mh = wid & 1, wn = wid >> 1, grp = lane >> 2, qq = lane & 3;
    int j0 = blockIdx.x * 8;
    size_t wrow = (size_t)(r >> 3)*p.NH + j0 + (r & 7);

    float cacc[4] = {0.f, 0.f, 0.f, 0.f};
    int buf = 0;
    kloop2(p.A1 + (size_t)r*p.K1, p.W1 + wrow*p.K1, p.K1,
           smx, cacc, r, c8, mh, wn, grp, qq, buf);
    if (p.K2)
        kloop2(p.A2 + (size_t)r*p.K2, p.W2 + wrow*p.K2, p.K2,
               smx, cacc, r, c8, mh, wn, grp, qq, buf);

    __syncthreads();
    float (*gsm)[33] = (float(*)[33])smx;
    int n = wn*8 + 2*qq;
    int b0 = mh*16 + grp;
    gsm[b0][n]   = cacc[0]; gsm[b0][n+1]   = cacc[1];
    gsm[b0+8][n] = cacc[2]; gsm[b0+8][n+1] = cacc[3];
    __syncthreads();

    int b = tid & 31, jj = tid >> 5, j = j0 + jj;
    size_t gb = (size_t)b * p.gaddB;
    float gi = gsm[b][jj]      + p.gadd[gb + 0*p.NH + j];
    float gf = gsm[b][8+jj]    + p.gadd[gb + 1*p.NH + j];
    float gg = gsm[b][16+jj]   + p.gadd[gb + 2*p.NH + j];
    float go = gsm[b][24+jj]   + p.gadd[gb + 3*p.NH + j];
    int ci = b*p.NH + j;
    float cc = sigf(gf)*p.cst[ci] + sigf(gi)*tanhf(gg);
    p.cst[ci] = cc;
    float hh = sigf(go)*tanhf(cc);
    p.hout[ci] = hh;
    if (p.out2) p.out2[(size_t)b*p.out2B + j] = hh;
}

// ---------------------------------------------------------------------------
// qgemm32: BM=32 GEMM (q = h1 @ Wa^T + bias), double-buffered kloop
// ---------------------------------------------------------------------------
__global__ __launch_bounds__(256) void qgemm32(
    const float* __restrict__ A, const unsigned* __restrict__ W,
    const float* __restrict__ bias, float* __restrict__ C, int K, int N)
{
    extern __shared__ unsigned smx[];
    int tid = threadIdx.x;
    int r = tid >> 3, c8 = tid & 7;
    int lane = tid & 31, wid = tid >> 5;
    int mh = wid & 1, wn = wid >> 1, grp = lane >> 2, qq = lane & 3;
    int n0 = blockIdx.x * 32;

    float cacc[4] = {0.f, 0.f, 0.f, 0.f};
    int buf = 0;
    kloop2(A + (size_t)r*K, W + (size_t)(n0 + r)*K, K,
           smx, cacc, r, c8, mh, wn, grp, qq, buf);

    int gn = n0 + wn*8 + 2*qq;
    int b0 = mh*16 + grp;
    C[(size_t)b0*N + gn]       = cacc[0] + bias[gn];
    C[(size_t)b0*N + gn + 1]   = cacc[1] + bias[gn+1];
    C[(size_t)(b0+8)*N + gn]   = cacc[2] + bias[gn];
    C[(size_t)(b0+8)*N + gn+1] = cacc[3] + bias[gn+1];
}

// ---------------------------------------------------------------------------
// decoder initial state
// ---------------------------------------------------------------------------
__global__ void dec_init() {
    int idx = blockIdx.x*256 + threadIdx.x;
    if (idx >= BB*HH) return;
    int b = idx >> 9, j = idx & 511;
    const int NP = BB*HH;
    float h0f = g_hbuf[(size_t)((0*2+0)*2+0)*NP + idx];
    float h0b = g_hbuf[(size_t)((0*2+1)*2+0)*NP + idx];
    float h1f = g_hbuf[(size_t)((1*2+0)*2+0)*NP + idx];
    float h1b = g_hbuf[(size_t)((1*2+1)*2+0)*NP + idx];
    float c0f = g_c[(size_t)(0*2+0)*NP + idx];
    float c0b = g_c[(size_t)(0*2+1)*NP + idx];
    float c1f = g_c[(size_t)(1*2+0)*NP + idx];
    float c1b = g_c[(size_t)(1*2+1)*NP + idx];
    g_dh0[b*DDm + j]      = h0f;  g_dh0[b*DDm + HH + j] = h0b;
    g_dc0[b*DDm + j]      = c0f;  g_dc0[b*DDm + HH + j] = c0b;
    g_dh1[b*DDm + j]      = h1f;  g_dh1[b*DDm + HH + j] = h1b;
    g_dc1[b*DDm + j]      = c1f;  g_dc1[b*DDm + HH + j] = c1b;
}

// ---------------------------------------------------------------------------
// attention scores: warp per (b,s). tanh.approx (scores path only).
// ---------------------------------------------------------------------------
__global__ __launch_bounds__(256) void att_scores2(const float* __restrict__ va) {
    int lane = threadIdx.x & 31, w = threadIdx.x >> 5;
    int task = blockIdx.x*8 + w;
    int b = task >> 6;
    const float* u  = g_Uenc + (size_t)task*DDm;
    const float* qq = g_q + (size_t)b*DDm;
    float p = 0.f;
    #pragma unroll 8
    for (int e = lane; e < DDm; e += 32)
        p += va[e]*tanha(qq[e] + u[e]);
    #pragma unroll
    for (int off = 16; off; off >>= 1)
        p += __shfl_xor_sync(0xffffffffu, p, off);
    if (lane == 0) g_sc[task] = p;
}

// ---------------------------------------------------------------------------
// softmax + context + target-embedding gather. grid 128 = (b, quarter).
// ---------------------------------------------------------------------------
__global__ __launch_bounds__(256) void softmax_ctx2(
    const int* __restrict__ y, const float* __restrict__ emb_tgt, int t)
{
    __shared__ float w[SS];
    int b = blockIdx.x >> 2, quarter = blockIdx.x & 3;
    int tid = threadIdx.x;
    if (tid < SS) w[tid] = g_sc[b*SS + tid];
    __syncthreads();
    if (tid == 0) {
        float mx = w[0];
        for (int s = 1; s < SS; s++) mx = fmaxf(mx, w[s]);
        float sm = 0.f;
        for (int s = 0; s < SS; s++) { w[s] = expf(w[s]-mx); sm += w[s]; }
        float inv = 1.0f/sm;
        for (int s = 0; s < SS; s++) w[s] *= inv;
    }
    __syncthreads();
    int d = quarter*256 + tid;
    {
        float acc = 0.f;
        const float* e = g_enc + (size_t)(b*SS)*DDm + d;
        #pragma unroll 8
        for (int s = 0; s < SS; s++) acc += w[s]*e[(size_t)s*DDm];
        g_xcat[(size_t)b*(EE+DDm) + EE + d] = acc;
    }
    if (quarter < 2) {
        int ei = quarter*256 + tid;
        int tok = y[b*TT + t];
        g_xcat[(size_t)b*(EE+DDm) + ei] = emb_tgt[(size_t)tok*EE + ei];
    }
}

// ---------------------------------------------------------------------------
// host driver
// ---------------------------------------------------------------------------
static float* symf(const void* s) {
    void* p = nullptr;
    cudaGetSymbolAddress(&p, s);
    return (float*)p;
}

extern "C" void kernel_launch(void* const* d_in, const int* in_sizes, int n_in,
                              void* d_out, int out_size) {
    const int*   x        = (const int*)  d_in[0];
    const int*   y        = (const int*)  d_in[1];
    const float* emb_src  = (const float*)d_in[2];
    const float* emb_tgt  = (const float*)d_in[3];
    const float* e0f_wih  = (const float*)d_in[4];
    const float* e0f_whh  = (const float*)d_in[5];
    const float* e0f_b    = (const float*)d_in[6];
    const float* e0b_wih  = (const float*)d_in[7];
    const float* e0b_whh  = (const float*)d_in[8];
    const float* e0b_b    = (const float*)d_in[9];
    const float* e1f_wih  = (const float*)d_in[10];
    const float* e1f_whh  = (const float*)d_in[11];
    const float* e1f_b    = (const float*)d_in[12];
    const float* e1b_wih  = (const float*)d_in[13];
    const float* e1b_whh  = (const float*)d_in[14];
    const float* e1b_b    = (const float*)d_in[15];
    const float* Wa_w     = (const float*)d_in[16];
    const float* Wa_b     = (const float*)d_in[17];
    const float* Ua_w     = (const float*)d_in[18];
    const float* Ua_b     = (const float*)d_in[19];
    const float* va_w     = (const float*)d_in[20];
    const float* d0_wih   = (const float*)d_in[21];
    const float* d0_whh   = (const float*)d_in[22];
    const float* d0_b     = (const float*)d_in[23];
    const float* d1_wih   = (const float*)d_in[24];
    const float* d1_whh   = (const float*)d_in[25];
    const float* d1_b     = (const float*)d_in[26];
    const float* fc_w     = (const float*)d_in[27];
    const float* fc_b     = (const float*)d_in[28];
    float* out = (float*)d_out;

    float* p_embx = symf(g_embx);
    float* p_xgF  = symf(g_xgF);
    float* p_xgB  = symf(g_xgB);
    float* p_in1  = symf(g_in1);
    float* p_enc  = symf(g_enc);
    float* p_Uenc = symf(g_Uenc);
    float* p_hbuf = symf(g_hbuf);
    float* p_c    = symf(g_c);
    float* p_dh0  = symf(g_dh0);
    float* p_dc0  = symf(g_dc0);
    float* p_dh1  = symf(g_dh1);
    float* p_dc1  = symf(g_dc1);
    float* p_q    = symf(g_q);
    float* p_xcat = symf(g_xcat);
    float* p_H1   = symf(g_H1);
    unsigned* p_w     = (unsigned*)symf(g_wcvt);
    unsigned* p_embxc = (unsigned*)symf(g_embxc);
    unsigned* p_in1c  = (unsigned*)symf(g_in1c);
    unsigned* p_encc  = (unsigned*)symf(g_encc);
    unsigned* p_H1c   = (unsigned*)symf(g_H1c);

    cudaFuncSetAttribute(cell32, cudaFuncAttributeMaxDynamicSharedMemorySize, CELL_SMEM);
    cudaFuncSetAttribute(qgemm32, cudaFuncAttributeMaxDynamicSharedMemorySize, CELL_SMEM);

    const int M = BB*SS;   // 2048

    // 0) convert all weights to split-bf16 pairs (vectorized)
    {
        struct { const float* s; size_t off; size_t n; } cv[15] = {
            { e0f_wih, OFF_E0F_WIH, 2048ull*512  },
            { e0b_wih, OFF_E0B_WIH, 2048ull*512  },
            { e1f_wih, OFF_E1F_WIH, 2048ull*1024 },
            { e1b_wih, OFF_E1B_WIH, 2048ull*1024 },
            { e0f_whh, OFF_E0F_WHH, 2048ull*512  },
            { e0b_whh, OFF_E0B_WHH, 2048ull*512  },
            { e1f_whh, OFF_E1F_WHH, 2048ull*512  },
            { e1b_whh, OFF_E1B_WHH, 2048ull*512  },
            { Ua_w,    OFF_UA,      1024ull*1024 },
            { Wa_w,    OFF_WA,      1024ull*1024 },
            { d0_wih,  OFF_D0WIH,   4096ull*1536 },
            { d0_whh,  OFF_D0WHH,   4096ull*1024 },
            { d1_wih,  OFF_D1WIH,   4096ull*1024 },
            { d1_whh,  OFF_D1WHH,   4096ull*1024 },
            { fc_w,    OFF_FC,      32000ull*1024 },
        };
        for (int i = 0; i < 15; i++)
            cvtW4<<<1024, 256>>>((const float4*)cv[i].s, (uint4*)(p_w + cv[i].off),
                                 (int)(cv[i].n/4));
    }

    // 1) embedding + reverse, then convert
    embed_rev_kernel<<<BB*SS, 128>>>(x, emb_src);
    cvtW4<<<1024, 256>>>((const float4*)p_embx, (uint4*)p_embxc, BB*SS*EE/4);

    // 2) layer-0 input GEMMs
    {
        dim3 grid(M/128, (4*HH)/128);
        bgemm128<<<grid, 256>>>(p_embxc, p_w + OFF_E0F_WIH, e0f_b, p_xgF, M, 4*HH, EE, 0);
        bgemm128<<<grid, 256>>>(p_embxc, p_w + OFF_E0B_WIH, e0b_b, p_xgB, M, 4*HH, EE, 0);
    }

    cudaMemsetAsync(p_hbuf, 0, sizeof(float)*2*2*2*BB*HH);
    cudaMemsetAsync(p_c,    0, sizeof(float)*2*2*BB*HH);

    // 3+5) encoder recurrences (fused gates+cell, both dirs per launch)
    const size_t whhOff[2][2] = { {OFF_E0F_WHH, OFF_E0B_WHH}, {OFF_E1F_WHH, OFF_E1B_WHH} };
    for (int layer = 0; layer < 2; layer++) {
        if (layer == 1) {
            cvtW4<<<1024, 256>>>((const float4*)p_in1, (uint4*)p_in1c, BB*SS*DDm/4);
            dim3 grid(M/128, (4*HH)/128);
            bgemm128<<<grid, 256>>>(p_in1c, p_w + OFF_E1F_WIH, e1f_b, p_xgF, M, 4*HH, DDm, 0);
            bgemm128<<<grid, 256>>>(p_in1c, p_w + OFF_E1B_WIH, e1b_b, p_xgB, M, 4*HH, DDm, 0);
        }
        float* outb = layer ? p_enc : p_in1;
        for (int s = 0; s < SS; s++) {
            int pp = s & 1;
            CArg a{}, bg{};
            a.A1 = p_hbuf + (size_t)((layer*2+0)*2 + pp)*(BB*HH);
            a.W1 = p_w + whhOff[layer][0]; a.K1 = HH;
            a.A2 = nullptr; a.W2 = nullptr; a.K2 = 0;
            a.NH = HH;
            a.gadd = p_xgF + (size_t)s*4*HH;  a.gaddB = SS*4*HH;
            a.cst  = p_c + (size_t)(layer*2+0)*(BB*HH);
            a.hout = p_hbuf + (size_t)((layer*2+0)*2 + (pp^1))*(BB*HH);
            a.out2 = outb + (size_t)s*DDm;    a.out2B = SS*DDm;
            int s1 = 63 - s;
            bg.A1 = p_hbuf + (size_t)((layer*2+1)*2 + pp)*(BB*HH);
            bg.W1 = p_w + whhOff[layer][1]; bg.K1 = HH;
            bg.A2 = nullptr; bg.W2 = nullptr; bg.K2 = 0;
            bg.NH = HH;
            bg.gadd = p_xgB + (size_t)s1*4*HH; bg.gaddB = SS*4*HH;
            bg.cst  = p_c + (size_t)(layer*2+1)*(BB*HH);
            bg.hout = p_hbuf + (size_t)((layer*2+1)*2 + (pp^1))*(BB*HH);
            bg.out2 = outb + (size_t)s1*DDm + HH; bg.out2B = SS*DDm;
            cell32<<<dim3(HH/8, 2), 256, CELL_SMEM>>>(a, bg);
        }
    }

    // 6) Uenc = enc @ Ua^T + Ua_b
    cvtW4<<<1024, 256>>>((const float4*)p_enc, (uint4*)p_encc, BB*SS*DDm/4);
    {
        dim3 grid(M/128, DDm/128);
        bgemm128<<<grid, 256>>>(p_encc, p_w + OFF_UA, Ua_b, p_Uenc, M, DDm, DDm, 0);
    }

    // 7) decoder initial state
    dec_init<<<(BB*HH + 255)/256, 256>>>();

    // 8) decoder steps (5 launches per step)
    for (int t = 0; t < TT-1; t++) {
        int pp = t & 1;
        float* h0r = p_dh0 + (size_t)pp*(BB*DDm);
        float* h0w = p_dh0 + (size_t)(pp^1)*(BB*DDm);
        float* h1r = p_dh1 + (size_t)pp*(BB*DDm);
        float* h1w = p_dh1 + (size_t)(pp^1)*(BB*DDm);

        qgemm32<<<DDm/32, 256, CELL_SMEM>>>(h1r, p_w + OFF_WA, Wa_b, p_q, DDm, DDm);
        att_scores2<<<256, 256>>>(va_w);
        softmax_ctx2<<<128, 256>>>(y, emb_tgt, t);

        CArg c0{};
        c0.A1 = p_xcat; c0.W1 = p_w + OFF_D0WIH; c0.K1 = EE+DDm;
        c0.A2 = h0r;    c0.W2 = p_w + OFF_D0WHH; c0.K2 = DDm;
        c0.NH = DDm; c0.gadd = d0_b; c0.gaddB = 0;
        c0.cst = p_dc0; c0.hout = h0w; c0.out2 = nullptr; c0.out2B = 0;
        cell32<<<dim3(DDm/8, 1), 256, CELL_SMEM>>>(c0, c0);

        CArg c1{};
        c1.A1 = h0w; c1.W1 = p_w + OFF_D1WIH; c1.K1 = DDm;
        c1.A2 = h1r; c1.W2 = p_w + OFF_D1WHH; c1.K2 = DDm;
        c1.NH = DDm; c1.gadd = d1_b; c1.gaddB = 0;
        c1.cst = p_dc1; c1.hout = h1w;
        c1.out2 = p_H1 + (size_t)t*BB*DDm; c1.out2B = DDm;
        cell32<<<dim3(DDm/8, 1), 256, CELL_SMEM>>>(c1, c1);
    }

    // 9) deferred logits GEMM: convert H1 (pad rows 2016..2047 with zeros)
    cudaMemsetAsync(p_H1c + 2016ull*DDm, 0, 32ull*DDm*sizeof(unsigned));
    cvtW4<<<1024, 256>>>((const float4*)p_H1, (uint4*)p_H1c, 63*BB*DDm/4);
    {
        int Mf = 63*BB;   // 2016
        dim3 grid(2048/128, VV/128);
        bgemm128<<<grid, 256>>>(p_H1c, p_w + OFF_FC, fc_b, out, Mf, VV, DDm, 1);
    }
}